// round 11
// baseline (speedup 1.0000x reference)
#include <cuda_runtime.h>
#include <cuda_bf16.h>
#include <cuda_fp16.h>
#include <math.h>
#include <stdint.h>

#define BB 2
#define LL 2048
#define DD 256
#define HH 8
#define HD 32
#define BH (BB*HH)
#define QT 16
#define SPITCH 2060
#define PHPITCH (SPITCH*2)

// ---------------- scratch (device globals; no allocation allowed) ----------
__device__ float         g_V  [(size_t)BH*LL*HD];
__device__ float         g_O  [(size_t)BH*LL*HD];
__device__ __nv_bfloat16 g_Q16[(size_t)BH*LL*64];    // rows [Qhi d0..31 | Qlo d0..31] (scaled)
__device__ __nv_bfloat16 g_K16[(size_t)BH*LL*64];    // rows [Khi | Klo]
__device__ __half        g_VT16[(size_t)BH*64*LL];   // [bh][hi d / 32+lo d][l]
__device__ float         g_E  [HH*LL];
__device__ float         g_rs [HH*LL];
__device__ float         g_dpart[(size_t)BB*HH*128*LL];
__device__ float         g_dpart2[16*BB*LL];

// ---------------- helpers ----------------------------------------------------
__device__ __forceinline__ float warpMax(float v){
    #pragma unroll
    for (int o=16;o;o>>=1) v = fmaxf(v, __shfl_xor_sync(0xffffffffu, v, o));
    return v;
}
__device__ __forceinline__ float warpSum(float v){
    #pragma unroll
    for (int o=16;o;o>>=1) v += __shfl_xor_sync(0xffffffffu, v, o);
    return v;
}
__device__ __forceinline__ void mma_bf16(float* c, const uint32_t* a,
                                         uint32_t b0, uint32_t b1){
    asm volatile(
        "mma.sync.aligned.m16n8k16.row.col.f32.bf16.bf16.f32 "
        "{%0,%1,%2,%3}, {%4,%5,%6,%7}, {%8,%9}, {%0,%1,%2,%3};"
        : "+f"(c[0]), "+f"(c[1]), "+f"(c[2]), "+f"(c[3])
        : "r"(a[0]), "r"(a[1]), "r"(a[2]), "r"(a[3]), "r"(b0), "r"(b1));
}
__device__ __forceinline__ void mma_f16(float* c, const uint32_t* a,
                                        uint32_t b0, uint32_t b1){
    asm volatile(
        "mma.sync.aligned.m16n8k16.row.col.f32.f16.f16.f32 "
        "{%0,%1,%2,%3}, {%4,%5,%6,%7}, {%8,%9}, {%0,%1,%2,%3};"
        : "+f"(c[0]), "+f"(c[1]), "+f"(c[2]), "+f"(c[3])
        : "r"(a[0]), "r"(a[1]), "r"(a[2]), "r"(a[3]), "r"(b0), "r"(b1));
}

// ---------------- kernel 1: QKV projection via mma (bf16 3-product split) ----
#define LK_XL (128*33)
#define LK_WH (2*128*33)
#define LK_WL (2*128*33 + 64*33)
#define LK_TOT (2*128*33 + 2*64*33)

__global__ __launch_bounds__(256) void qkv_mma_kernel(
    const float* __restrict__ x,
    const float* __restrict__ Wq, const float* __restrict__ bq,
    const float* __restrict__ Wk, const float* __restrict__ bk,
    const float* __restrict__ Wv, const float* __restrict__ bv)
{
    extern __shared__ uint32_t usm[];
    uint32_t* Xh = usm;
    uint32_t* Xl = usm + LK_XL;
    uint32_t* Wh = usm + LK_WH;
    uint32_t* Wl = usm + LK_WL;

    const float* Wm; const float* bm;
    if (blockIdx.z == 0)      { Wm=Wq; bm=bq; }
    else if (blockIdx.z == 1) { Wm=Wk; bm=bk; }
    else                      { Wm=Wv; bm=bv; }

    const int m0 = blockIdx.y*128, n0 = blockIdx.x*64;
    const int tid = threadIdx.x, wid = tid>>5, lane = tid&31;
    const int gr = lane>>2, kp = lane&3;

    float c[8][4] = {};
    for (int kc = 0; kc < 4; kc++) {
        __syncthreads();
        #pragma unroll
        for (int j = 0; j < 16; j++) {
            int u2 = tid + j*256;
            int r = u2 >> 5, cc = u2 & 31;
            float2 v = *(const float2*)&x[(size_t)(m0+r)*DD + kc*64 + cc*2];
            __nv_bfloat162 hb = __floats2bfloat162_rn(v.x, v.y);
            __nv_bfloat162 lb = __floats2bfloat162_rn(
                v.x - __bfloat162float(hb.x), v.y - __bfloat162float(hb.y));
            Xh[r*33 + cc] = *(const uint32_t*)&hb;
            Xl[r*33 + cc] = *(const uint32_t*)&lb;
        }
        #pragma unroll
        for (int j = 0; j < 8; j++) {
            int u2 = tid + j*256;
            int r = u2 >> 5, cc = u2 & 31;
            float2 v = *(const float2*)&Wm[(size_t)(n0+r)*DD + kc*64 + cc*2];
            __nv_bfloat162 hb = __floats2bfloat162_rn(v.x, v.y);
            __nv_bfloat162 lb = __floats2bfloat162_rn(
                v.x - __bfloat162float(hb.x), v.y - __bfloat162float(hb.y));
            Wh[r*33 + cc] = *(const uint32_t*)&hb;
            Wl[r*33 + cc] = *(const uint32_t*)&lb;
        }
        __syncthreads();
        #pragma unroll
        for (int s = 0; s < 4; s++) {
            const int mb = wid*16;
            uint32_t ah[4], al[4];
            ah[0] = Xh[(mb+gr  )*33 + s*8 + kp];
            ah[1] = Xh[(mb+gr+8)*33 + s*8 + kp];
            ah[2] = Xh[(mb+gr  )*33 + s*8 + kp + 4];
            ah[3] = Xh[(mb+gr+8)*33 + s*8 + kp + 4];
            al[0] = Xl[(mb+gr  )*33 + s*8 + kp];
            al[1] = Xl[(mb+gr+8)*33 + s*8 + kp];
            al[2] = Xl[(mb+gr  )*33 + s*8 + kp + 4];
            al[3] = Xl[(mb+gr+8)*33 + s*8 + kp + 4];
            #pragma unroll
            for (int nt = 0; nt < 8; nt++) {
                uint32_t bh0 = Wh[(nt*8+gr)*33 + s*8 + kp];
                uint32_t bh1 = Wh[(nt*8+gr)*33 + s*8 + kp + 4];
                uint32_t bl0 = Wl[(nt*8+gr)*33 + s*8 + kp];
                uint32_t bl1 = Wl[(nt*8+gr)*33 + s*8 + kp + 4];
                mma_bf16(c[nt], ah, bh0, bh1);
                mma_bf16(c[nt], ah, bl0, bl1);
                mma_bf16(c[nt], al, bh0, bh1);
            }
        }
    }
    const float SCALE = 0.17677669529663687f;
    #pragma unroll
    for (int nt = 0; nt < 8; nt++) {
        #pragma unroll
        for (int hf = 0; hf < 2; hf++) {
            int m = m0 + wid*16 + gr + hf*8;
            int b = m >> 11, l = m & (LL-1);
            #pragma unroll
            for (int e = 0; e < 2; e++) {
                int n = n0 + nt*8 + kp*2 + e;
                float v = c[nt][hf*2 + e] + bm[n];
                int h = n >> 5, d = n & 31;
                size_t row = (size_t)(b*HH + h)*LL + l;
                if (blockIdx.z == 0) {
                    float sv = v * SCALE;
                    __nv_bfloat16 hi = __float2bfloat16(sv);
                    g_Q16[row*64 + d]      = hi;
                    g_Q16[row*64 + 32 + d] = __float2bfloat16(sv - __bfloat162float(hi));
                } else if (blockIdx.z == 1) {
                    __nv_bfloat16 hi = __float2bfloat16(v);
                    g_K16[row*64 + d]      = hi;
                    g_K16[row*64 + 32 + d] = __float2bfloat16(v - __bfloat162float(hi));
                } else {
                    g_V[row*HD + d] = v;
                }
            }
        }
    }
}

// ---------------- kernel 1b: V transpose + f16 hi/lo -------------------------
__global__ __launch_bounds__(256) void vt_kernel()
{
    __shared__ float Vsm[128][33];
    const int bh = blockIdx.x, l0 = blockIdx.y*128;
    const int tid = threadIdx.x;
    for (int idx = tid; idx < 128*32; idx += 256) {
        int i = idx >> 5, d = idx & 31;
        Vsm[i][d] = g_V[((size_t)bh*LL + l0 + i)*HD + d];
    }
    __syncthreads();
    for (int idx = tid; idx < 32*128; idx += 256) {
        int d = idx >> 7, i = idx & 127;
        float v = Vsm[i][d];
        __half hi = __float2half_rn(v);
        __half lo = __float2half_rn(v - __half2float(hi));
        g_VT16[((size_t)bh*64 + d)*LL + l0 + i]      = hi;
        g_VT16[((size_t)bh*64 + 32 + d)*LL + l0 + i] = lo;
    }
}

// ---------------- kernel 2: prior tables via prefix sum ----------------------
__global__ __launch_bounds__(256) void prior_kernel(const float* __restrict__ u)
{
    __shared__ float Es[LL];
    __shared__ float Ps[LL];
    __shared__ float part[256];
    const int h = blockIdx.x, tid = threadIdx.x;
    float uv = u[h];
    float cc = 0.5f / (uv*uv + 1e-6f);
    #pragma unroll
    for (int j = 0; j < 8; j++) {
        int d = tid + j*256;
        float fd = (float)d;
        float e = expf(-(fd*fd)*cc);
        Es[d] = e;
        g_E[h*LL + d] = e;
    }
    __syncthreads();
    float s = 0.f;
    #pragma unroll
    for (int i = 0; i < 8; i++) s += Es[tid*8 + i];
    part[tid] = s;
    __syncthreads();
    if (tid == 0) {
        float run = 0.f;
        for (int i = 0; i < 256; i++) { run += part[i]; part[i] = run; }
    }
    __syncthreads();
    float run = (tid == 0) ? 0.f : part[tid-1];
    #pragma unroll
    for (int i = 0; i < 8; i++) {
        run += Es[tid*8 + i];
        Ps[tid*8 + i] = run;
    }
    __syncthreads();
    float e0 = Es[0];
    #pragma unroll
    for (int j = 0; j < 8; j++) {
        int q = tid + j*256;
        g_rs[h*LL + q] = Ps[q] + Ps[LL-1-q] - e0;
    }
}

// ---------------- kernel 3: FUSED scores+softmax+disc+AV via mma.sync --------
#define SMF_R2   32960
#define SMF_ES   49600
#define SMF_QST  51648
#define SMF_IRS  52176
#define SMF_TOT  52192
#define SMF_BYTES (SMF_TOT*4)

__global__ __launch_bounds__(512,1) void attn_fused_kernel()
{
    extern __shared__ float sm[];
    float*    Srow = sm;
    uint32_t* PU   = (uint32_t*)sm;
    uint32_t* R2   = (uint32_t*)(sm + SMF_R2);
    float*    Es   = sm + SMF_ES;
    float*    Op   = sm + SMF_ES;
    uint32_t* Qst  = (uint32_t*)(sm + SMF_QST);
    float*    irs  = sm + SMF_IRS;

    const int tid = threadIdx.x, wid = tid >> 5, lane = tid & 31;
    const int gr = lane >> 2, kp = lane & 3;
    const int qt = blockIdx.x, bh = blockIdx.y;
    const int b = bh >> 3, h = bh & 7, q0 = qt * QT;

    {
        int r = tid >> 5, c = tid & 31;
        Qst[r*33 + c] = ((const uint32_t*)g_Q16)[((size_t)bh*LL + q0 + r)*32 + c];
    }
    for (int i = tid; i < LL; i += 512) Es[i] = g_E[h*LL + i];
    if (tid < QT) irs[tid] = 1.0f / (g_rs[h*LL + q0 + tid] + 1e-6f);
    __syncthreads();

    uint32_t qa[2][2][4];
    #pragma unroll
    for (int p = 0; p < 2; p++){
        int base = p*16;
        #pragma unroll
        for (int s = 0; s < 2; s++){
            qa[p][s][0] = Qst[ gr    *33 + base + kp     + 8*s];
            qa[p][s][1] = Qst[(gr+8) *33 + base + kp     + 8*s];
            qa[p][s][2] = Qst[ gr    *33 + base + kp + 4 + 8*s];
            qa[p][s][3] = Qst[(gr+8) *33 + base + kp + 4 + 8*s];
        }
    }

    // ---- phase 1: scores, 8 chunks of 256 keys, register-prefetched ---------
    {
        const uint4* Gk4 = (const uint4*)g_K16;
        const int key = (tid) >> 2, q4 = tid & 3;        // j=0 slot
        const int key1 = (tid + 512) >> 2, q41 = (tid + 512) & 3; // j=1 slot
        uint4 pk[4];
        {
            size_t r0 = (size_t)bh*LL + key;
            size_t r1 = (size_t)bh*LL + key1;
            pk[0] = Gk4[r0*8 + q4];  pk[1] = Gk4[r0*8 + 4 + q4];
            pk[2] = Gk4[r1*8 + q41]; pk[3] = Gk4[r1*8 + 4 + q41];
        }
        for (int kc = 0; kc < 8; kc++) {
            __syncthreads();
            *(uint4*)(R2 + key *20 + q4 *4)        = pk[0];
            *(uint4*)(R2 + 5120 + key *20 + q4 *4) = pk[1];
            *(uint4*)(R2 + key1*20 + q41*4)        = pk[2];
            *(uint4*)(R2 + 5120 + key1*20 + q41*4) = pk[3];
            __syncthreads();
            if (kc < 7) {
                size_t r0 = (size_t)bh*LL + (kc+1)*256 + key;
                size_t r1 = (size_t)bh*LL + (kc+1)*256 + key1;
                pk[0] = Gk4[r0*8 + q4];  pk[1] = Gk4[r0*8 + 4 + q4];
                pk[2] = Gk4[r1*8 + q41]; pk[3] = Gk4[r1*8 + 4 + q41];
            }
            #pragma unroll
            for (int t = 0; t < 2; t++) {
                int nt = wid*2 + t;
                int n0 = nt*8;
                float c[4] = {0.f,0.f,0.f,0.f};
                #pragma unroll
                for (int s = 0; s < 2; s++) {
                    uint32_t bh0 = R2[(n0+gr)*20 + kp     + 8*s];
                    uint32_t bh1 = R2[(n0+gr)*20 + kp + 4 + 8*s];
                    uint32_t bl0 = R2[5120 + (n0+gr)*20 + kp     + 8*s];
                    uint32_t bl1 = R2[5120 + (n0+gr)*20 + kp + 4 + 8*s];
                    mma_bf16(c, qa[0][s], bh0, bh1);
                    mma_bf16(c, qa[0][s], bl0, bl1);
                    mma_bf16(c, qa[1][s], bh0, bh1);
                }
                int col = kc*256 + n0 + kp*2;
                *(float2*)&Srow[ gr   *SPITCH + col] = make_float2(c[0], c[1]);
                *(float2*)&Srow[(gr+8)*SPITCH + col] = make_float2(c[2], c[3]);
            }
        }
    }
    __syncthreads();

    // ---- phase 2: softmax (float4 passes), in-place normalized f16 ----------
    {
        float* R = Srow + wid*SPITCH;
        const float4* R4 = (const float4*)R;
        float4* W4 = (float4*)R;
        float m = -3.4e38f;
        #pragma unroll
        for (int i = 0; i < 16; i++) {
            float4 v = R4[i*32 + lane];
            m = fmaxf(m, fmaxf(fmaxf(v.x, v.y), fmaxf(v.z, v.w)));
        }
        m = warpMax(m);
        float s = 0.f;
        #pragma unroll
        for (int i = 0; i < 16; i++) {
            float4 v = R4[i*32 + lane];
            v.x = __expf(v.x - m); v.y = __expf(v.y - m);
            v.z = __expf(v.z - m); v.w = __expf(v.w - m);
            s += v.x + v.y + v.z + v.w;
            W4[i*32 + lane] = v;
        }
        s = warpSum(s);
        float iv = 1.0f / s;
        uint2* W2 = (uint2*)R;
        #pragma unroll
        for (int i = 0; i < 16; i++) {
            float4 v = R4[i*32 + lane];
            __syncwarp();
            __half2 p0 = __floats2half2_rn(v.x*iv, v.y*iv);
            __half2 p1 = __floats2half2_rn(v.z*iv, v.w*iv);
            uint2 o;
            o.x = *(const uint32_t*)&p0;
            o.y = *(const uint32_t*)&p1;
            W2[i*32 + lane] = o;
        }
    }
    __syncthreads();

    // prefetch V chunk 0 (overlaps with phase 3)
    const uint4* Gv4 = (const uint4*)g_VT16;
    uint4 pv[8];
    #pragma unroll
    for (int j = 0; j < 4; j++) {
        int u2 = tid + j*512;
        int d = u2 >> 6, p4 = u2 & 63;
        pv[j*2]   = Gv4[((size_t)bh*64 + d)*256      + p4];
        pv[j*2+1] = Gv4[((size_t)bh*64 + 32 + d)*256 + p4];
    }

    // ---- phase 3: discrepancy partials (half2 reads, float2 stores) ---------
    {
        size_t pbase = (((size_t)(b*HH + h))*128 + qt) * LL;
        #pragma unroll
        for (int t = 0; t < 2; t++) {
            int k2 = tid + t*512;
            int k  = k2*2;
            float2 acc = make_float2(0.f, 0.f);
            #pragma unroll
            for (int q = 0; q < QT; q++) {
                uint32_t pa = PU[q*SPITCH + k2];
                __half2 h2 = *(const __half2*)&pa;
                float2 af = __half22float2(h2);
                float pr0 = Es[abs(q0 + q - k)]     * irs[q];
                float pr1 = Es[abs(q0 + q - k - 1)] * irs[q];
                acc.x += fabsf(af.x - pr0);
                acc.y += fabsf(af.y - pr1);
            }
            *(float2*)&g_dpart[pbase + k] = acc;
        }
    }

    // ---- phase 4: O = P @ V via mma.f16, register-prefetched ----------------
    {
        const int nt = wid & 3, seg = wid >> 2;
        uint32_t* Vhi = R2;
        uint32_t* Vlo = R2 + 8320;
        float c[4] = {0.f,0.f,0.f,0.f};

        for (int ch = 0; ch < 4; ch++) {
            __syncthreads();
            #pragma unroll
            for (int j = 0; j < 4; j++) {
                int u2 = tid + j*512;
                int d = u2 >> 6, p4 = u2 & 63;
                *(uint4*)(Vhi + d*260 + p4*4) = pv[j*2];
                *(uint4*)(Vlo + d*260 + p4*4) = pv[j*2+1];
            }
            __syncthreads();
            if (ch < 3) {
                #pragma unroll
                for (int j = 0; j < 4; j++) {
                    int u2 = tid + j*512;
                    int d = u2 >> 6, p4 = u2 & 63;
                    pv[j*2]   = Gv4[((size_t)bh*64 + d)*256      + (ch+1)*64 + p4];
                    pv[j*2+1] = Gv4[((size_t)bh*64 + 32 + d)*256 + (ch+1)*64 + p4];
                }
            }
            #pragma unroll
            for (int ks = 0; ks < 8; ks++) {
                int kg2 = ch*256 + seg*64 + ks*8;
                uint32_t a[4];
                a[0] = PU[ gr   *SPITCH + kg2 + kp];
                a[1] = PU[(gr+8)*SPITCH + kg2 + kp];
                a[2] = PU[ gr   *SPITCH + kg2 + kp + 4];
                a[3] = PU[(gr+8)*SPITCH + kg2 + kp + 4];
                int kb = seg*64 + ks*8;
                uint32_t bh0 = Vhi[(nt*8+gr)*260 + kb + kp];
                uint32_t bh1 = Vhi[(nt*8+gr)*260 + kb + kp + 4];
                uint32_t bl0 = Vlo[(nt*8+gr)*260 + kb + kp];
                uint32_t bl1 = Vlo[(nt*8+gr)*260 + kb + kp + 4];
                mma_f16(c, a, bh0, bh1);
                mma_f16(c, a, bl0, bl1);
            }
        }
        __syncthreads();
        int dcol = nt*8 + kp*2;
        Op[seg*512 +  gr   *32 + dcol]     = c[0];
        Op[seg*512 +  gr   *32 + dcol + 1] = c[1];
        Op[seg*512 + (gr+8)*32 + dcol]     = c[2];
        Op[seg*512 + (gr+8)*32 + dcol + 1] = c[3];
    }
    __syncthreads();
    {
        int q = tid >> 5, d = tid & 31;
        float s = Op[q*32 + d] + Op[512 + q*32 + d]
                + Op[1024 + q*32 + d] + Op[1536 + q*32 + d];
        g_O[((size_t)bh*LL + q0 + q)*HD + d] = s;
    }
}

// ---------------- kernel 4: discrepancy reduce (2-stage) ----------------------
__global__ void disc_reduce1_kernel()
{
    int k = blockIdx.x*256 + threadIdx.x;
    int seg = blockIdx.y;
    int b = k >> 11, kk = k & (LL-1);
    const float* base = g_dpart + (size_t)b*HH*128*LL + kk;
    float s = 0.f;
    #pragma unroll 8
    for (int p = seg*64; p < seg*64 + 64; p++) s += base[(size_t)p*LL];
    g_dpart2[seg*BB*LL + k] = s;
}
__global__ void disc_reduce2_kernel(float* __restrict__ dout)
{
    int idx = blockIdx.x*256 + threadIdx.x;
    float s = 0.f;
    #pragma unroll
    for (int seg = 0; seg < 16; seg++) s += g_dpart2[seg*BB*LL + idx];
    dout[idx] = s * (1.0f/(HH*(float)LL));
}

// ---------------- kernel 5: out projection via mma ---------------------------
__global__ __launch_bounds__(256) void outproj_mma_kernel(
    const float* __restrict__ Wo, const float* __restrict__ bo,
    float* __restrict__ out)
{
    extern __shared__ uint32_t usm[];
    uint32_t* Xh = usm;
    uint32_t* Xl = usm + LK_XL;
    uint32_t* Wh = usm + LK_WH;
    uint32_t* Wl = usm + LK_WL;

    const int m0 = blockIdx.y*128, n0 = blockIdx.x*64;
    const int tid = threadIdx.x, wid = tid>>5, lane = tid&31;
    const int gr = lane>>2, kp = lane&3;

    float c[8][4] = {};
    for (int kc = 0; kc < 4; kc++) {
        __syncthreads();
        #pragma unroll
        for (int j = 0; j < 16; j++) {
            int u2 = tid + j*256;
            int r = u2 >> 5, cc = u2 & 31;
            int m = m0 + r;
            int b = m >> 11, l = m & (LL-1);
            int k = kc*64 + cc*2;
            int hh = k >> 5, d = k & 31;
            float2 v = *(const float2*)&g_O[(((size_t)(b*HH + hh))*LL + l)*HD + d];
            __nv_bfloat162 hb = __floats2bfloat162_rn(v.x, v.y);
            __nv_bfloat162 lb = __floats2bfloat162_rn(
                v.x - __bfloat162float(hb.x), v.y - __bfloat162float(hb.y));
            Xh[r*33 + cc] = *(const uint32_t*)&hb;
            Xl[r*33 + cc] = *(const uint32_t*)&lb;
        }
        #pragma unroll
        for (int j = 0; j < 8; j++) {
            int u2 = tid + j*256;
            int r = u2 >> 5, cc = u2 & 31;
            float2 v = *(const float2*)&Wo[(size_t)(n0+r)*DD + kc*64 + cc*2];
            __nv_bfloat162 hb = __floats2bfloat162_rn(v.x, v.y);
            __nv_bfloat162 lb = __floats2bfloat162_rn(
                v.x - __bfloat162float(hb.x), v.y - __bfloat162float(hb.y));
            Wh[r*33 + cc] = *(const uint32_t*)&hb;
            Wl[r*33 + cc] = *(const uint32_t*)&lb;
        }
        __syncthreads();
        #pragma unroll
        for (int s = 0; s < 4; s++) {
            const int mb = wid*16;
            uint32_t ah[4], al[4];
            ah[0] = Xh[(mb+gr  )*33 + s*8 + kp];
            ah[1] = Xh[(mb+gr+8)*33 + s*8 + kp];
            ah[2] = Xh[(mb+gr  )*33 + s*8 + kp + 4];
            ah[3] = Xh[(mb+gr+8)*33 + s*8 + kp + 4];
            al[0] = Xl[(mb+gr  )*33 + s*8 + kp];
            al[1] = Xl[(mb+gr+8)*33 + s*8 + kp];
            al[2] = Xl[(mb+gr  )*33 + s*8 + kp + 4];
            al[3] = Xl[(mb+gr+8)*33 + s*8 + kp + 4];
            #pragma unroll
            for (int nt = 0; nt < 8; nt++) {
                uint32_t bh0 = Wh[(nt*8+gr)*33 + s*8 + kp];
                uint32_t bh1 = Wh[(nt*8+gr)*33 + s*8 + kp + 4];
                uint32_t bl0 = Wl[(nt*8+gr)*33 + s*8 + kp];
                uint32_t bl1 = Wl[(nt*8+gr)*33 + s*8 + kp + 4];
                mma_bf16(c[nt], ah, bh0, bh1);
                mma_bf16(c[nt], ah, bl0, bl1);
                mma_bf16(c[nt], al, bh0, bh1);
            }
        }
    }
    #pragma unroll
    for (int nt = 0; nt < 8; nt++) {
        #pragma unroll
        for (int hf = 0; hf < 2; hf++) {
            int m = m0 + wid*16 + gr + hf*8;
            int n = n0 + nt*8 + kp*2;
            float2 o;
            o.x = c[nt][hf*2]     + bo[n];
            o.y = c[nt][hf*2 + 1] + bo[n+1];
            *(float2*)&out[(size_t)m*DD + n] = o;
        }
    }
}

// ---------------- launch --------------------------------------------------------
extern "C" void kernel_launch(void* const* d_in, const int* in_sizes, int n_in,
                              void* d_out, int out_size)
{
    const float* x  = (const float*)d_in[0];
    const float* Wq = (const float*)d_in[1];
    const float* bq = (const float*)d_in[2];
    const float* Wk = (const float*)d_in[3];
    const float* bk = (const float*)d_in[4];
    const float* Wv = (const float*)d_in[5];
    const float* bv = (const float*)d_in[6];
    const float* u  = (const float*)d_in[7];
    const float* Wo = (const float*)d_in[8];
    const float* bo = (const float*)d_in[9];
    float* out = (float*)d_out;

    cudaFuncSetAttribute(attn_fused_kernel,
                         cudaFuncAttributeMaxDynamicSharedMemorySize, SMF_BYTES);
    cudaFuncSetAttribute(qkv_mma_kernel,
                         cudaFuncAttributeMaxDynamicSharedMemorySize, LK_TOT*4);
    cudaFuncSetAttribute(outproj_mma_kernel,
                         cudaFuncAttributeMaxDynamicSharedMemorySize, LK_TOT*4);

    qkv_mma_kernel<<<dim3(DD/64, (BB*LL)/128, 3), 256, LK_TOT*4>>>(
        x, Wq, bq, Wk, bk, Wv, bv);
    vt_kernel<<<dim3(BH, LL/128), 256>>>();
    prior_kernel<<<HH, 256>>>(u);
    attn_fused_kernel<<<dim3(LL/QT, BH), 512, SMF_BYTES>>>();
    disc_reduce1_kernel<<<dim3((BB*LL)/256, 16), 256>>>();
    disc_reduce2_kernel<<<(BB*LL)/256, 256>>>(out + (size_t)BB*LL*DD);
    outproj_mma_kernel<<<dim3(DD/64, (BB*LL)/128), 256, LK_TOT*4>>>(Wo, bo, out);
}

// round 12
// speedup vs baseline: 1.0343x; 1.0343x over previous
#include <cuda_runtime.h>
#include <cuda_bf16.h>
#include <cuda_fp16.h>
#include <math.h>
#include <stdint.h>

#define BB 2
#define LL 2048
#define DD 256
#define HH 8
#define HD 32
#define BH (BB*HH)
#define QT 16
#define SPITCH 2060
#define PHPITCH (SPITCH*2)

// ---------------- scratch (device globals; no allocation allowed) ----------
__device__ float         g_V  [(size_t)BH*LL*HD];
__device__ float         g_O  [(size_t)BH*LL*HD];
__device__ __nv_bfloat16 g_Q16[(size_t)BH*LL*64];    // rows [Qhi d0..31 | Qlo d0..31] (scaled)
__device__ __nv_bfloat16 g_K16[(size_t)BH*LL*64];    // rows [Khi | Klo]
__device__ __half        g_VT16[(size_t)BH*64*LL];   // [bh][hi d / 32+lo d][l]
__device__ float         g_E  [HH*LL];
__device__ float         g_rs [HH*LL];
__device__ float         g_dpart[(size_t)BB*HH*128*LL];
__device__ float         g_dpart2[16*BB*LL];

// ---------------- helpers ----------------------------------------------------
__device__ __forceinline__ uint32_t smem_u32(const void* p){
    uint32_t a;
    asm("{ .reg .u64 t; cvta.to.shared.u64 t, %1; cvt.u32.u64 %0, t; }" : "=r"(a) : "l"(p));
    return a;
}
__device__ __forceinline__ float warpMax(float v){
    #pragma unroll
    for (int o=16;o;o>>=1) v = fmaxf(v, __shfl_xor_sync(0xffffffffu, v, o));
    return v;
}
__device__ __forceinline__ float warpSum(float v){
    #pragma unroll
    for (int o=16;o;o>>=1) v += __shfl_xor_sync(0xffffffffu, v, o);
    return v;
}
__device__ __forceinline__ void mma_bf16(float* c, const uint32_t* a,
                                         uint32_t b0, uint32_t b1){
    asm volatile(
        "mma.sync.aligned.m16n8k16.row.col.f32.bf16.bf16.f32 "
        "{%0,%1,%2,%3}, {%4,%5,%6,%7}, {%8,%9}, {%0,%1,%2,%3};"
        : "+f"(c[0]), "+f"(c[1]), "+f"(c[2]), "+f"(c[3])
        : "r"(a[0]), "r"(a[1]), "r"(a[2]), "r"(a[3]), "r"(b0), "r"(b1));
}
__device__ __forceinline__ void mma_f16(float* c, const uint32_t* a,
                                        uint32_t b0, uint32_t b1){
    asm volatile(
        "mma.sync.aligned.m16n8k16.row.col.f32.f16.f16.f32 "
        "{%0,%1,%2,%3}, {%4,%5,%6,%7}, {%8,%9}, {%0,%1,%2,%3};"
        : "+f"(c[0]), "+f"(c[1]), "+f"(c[2]), "+f"(c[3])
        : "r"(a[0]), "r"(a[1]), "r"(a[2]), "r"(a[3]), "r"(b0), "r"(b1));
}
__device__ __forceinline__ void ldmx4(uint32_t* r, uint32_t addr){
    asm volatile("ldmatrix.sync.aligned.m8n8.x4.shared.b16 {%0,%1,%2,%3}, [%4];"
        : "=r"(r[0]),"=r"(r[1]),"=r"(r[2]),"=r"(r[3]) : "r"(addr));
}
__device__ __forceinline__ void ldmx2(uint32_t* r, uint32_t addr){
    asm volatile("ldmatrix.sync.aligned.m8n8.x2.shared.b16 {%0,%1}, [%2];"
        : "=r"(r[0]),"=r"(r[1]) : "r"(addr));
}

// ---------------- kernel 1: QKV projection via mma (bf16 3-product split) ----
#define LK_XL (128*33)
#define LK_WH (2*128*33)
#define LK_WL (2*128*33 + 64*33)
#define LK_TOT (2*128*33 + 2*64*33)

__global__ __launch_bounds__(256) void qkv_mma_kernel(
    const float* __restrict__ x,
    const float* __restrict__ Wq, const float* __restrict__ bq,
    const float* __restrict__ Wk, const float* __restrict__ bk,
    const float* __restrict__ Wv, const float* __restrict__ bv)
{
    extern __shared__ uint32_t usm[];
    uint32_t* Xh = usm;
    uint32_t* Xl = usm + LK_XL;
    uint32_t* Wh = usm + LK_WH;
    uint32_t* Wl = usm + LK_WL;

    const float* Wm; const float* bm;
    if (blockIdx.z == 0)      { Wm=Wq; bm=bq; }
    else if (blockIdx.z == 1) { Wm=Wk; bm=bk; }
    else                      { Wm=Wv; bm=bv; }

    const int m0 = blockIdx.y*128, n0 = blockIdx.x*64;
    const int tid = threadIdx.x, wid = tid>>5, lane = tid&31;
    const int gr = lane>>2, kp = lane&3;

    float c[8][4] = {};
    for (int kc = 0; kc < 4; kc++) {
        __syncthreads();
        #pragma unroll
        for (int j = 0; j < 16; j++) {
            int u2 = tid + j*256;
            int r = u2 >> 5, cc = u2 & 31;
            float2 v = *(const float2*)&x[(size_t)(m0+r)*DD + kc*64 + cc*2];
            __nv_bfloat162 hb = __floats2bfloat162_rn(v.x, v.y);
            __nv_bfloat162 lb = __floats2bfloat162_rn(
                v.x - __bfloat162float(hb.x), v.y - __bfloat162float(hb.y));
            Xh[r*33 + cc] = *(const uint32_t*)&hb;
            Xl[r*33 + cc] = *(const uint32_t*)&lb;
        }
        #pragma unroll
        for (int j = 0; j < 8; j++) {
            int u2 = tid + j*256;
            int r = u2 >> 5, cc = u2 & 31;
            float2 v = *(const float2*)&Wm[(size_t)(n0+r)*DD + kc*64 + cc*2];
            __nv_bfloat162 hb = __floats2bfloat162_rn(v.x, v.y);
            __nv_bfloat162 lb = __floats2bfloat162_rn(
                v.x - __bfloat162float(hb.x), v.y - __bfloat162float(hb.y));
            Wh[r*33 + cc] = *(const uint32_t*)&hb;
            Wl[r*33 + cc] = *(const uint32_t*)&lb;
        }
        __syncthreads();
        #pragma unroll
        for (int s = 0; s < 4; s++) {
            const int mb = wid*16;
            uint32_t ah[4], al[4];
            ah[0] = Xh[(mb+gr  )*33 + s*8 + kp];
            ah[1] = Xh[(mb+gr+8)*33 + s*8 + kp];
            ah[2] = Xh[(mb+gr  )*33 + s*8 + kp + 4];
            ah[3] = Xh[(mb+gr+8)*33 + s*8 + kp + 4];
            al[0] = Xl[(mb+gr  )*33 + s*8 + kp];
            al[1] = Xl[(mb+gr+8)*33 + s*8 + kp];
            al[2] = Xl[(mb+gr  )*33 + s*8 + kp + 4];
            al[3] = Xl[(mb+gr+8)*33 + s*8 + kp + 4];
            #pragma unroll
            for (int nt = 0; nt < 8; nt++) {
                uint32_t bh0 = Wh[(nt*8+gr)*33 + s*8 + kp];
                uint32_t bh1 = Wh[(nt*8+gr)*33 + s*8 + kp + 4];
                uint32_t bl0 = Wl[(nt*8+gr)*33 + s*8 + kp];
                uint32_t bl1 = Wl[(nt*8+gr)*33 + s*8 + kp + 4];
                mma_bf16(c[nt], ah, bh0, bh1);
                mma_bf16(c[nt], ah, bl0, bl1);
                mma_bf16(c[nt], al, bh0, bh1);
            }
        }
    }
    const float SCALE = 0.17677669529663687f;
    #pragma unroll
    for (int nt = 0; nt < 8; nt++) {
        #pragma unroll
        for (int hf = 0; hf < 2; hf++) {
            int m = m0 + wid*16 + gr + hf*8;
            int b = m >> 11, l = m & (LL-1);
            #pragma unroll
            for (int e = 0; e < 2; e++) {
                int n = n0 + nt*8 + kp*2 + e;
                float v = c[nt][hf*2 + e] + bm[n];
                int h = n >> 5, d = n & 31;
                size_t row = (size_t)(b*HH + h)*LL + l;
                if (blockIdx.z == 0) {
                    float sv = v * SCALE;
                    __nv_bfloat16 hi = __float2bfloat16(sv);
                    g_Q16[row*64 + d]      = hi;
                    g_Q16[row*64 + 32 + d] = __float2bfloat16(sv - __bfloat162float(hi));
                } else if (blockIdx.z == 1) {
                    __nv_bfloat16 hi = __float2bfloat16(v);
                    g_K16[row*64 + d]      = hi;
                    g_K16[row*64 + 32 + d] = __float2bfloat16(v - __bfloat162float(hi));
                } else {
                    g_V[row*HD + d] = v;
                }
            }
        }
    }
}

// ---------------- kernel 1b: V transpose + f16 hi/lo -------------------------
__global__ __launch_bounds__(256) void vt_kernel()
{
    __shared__ float Vsm[128][33];
    const int bh = blockIdx.x, l0 = blockIdx.y*128;
    const int tid = threadIdx.x;
    for (int idx = tid; idx < 128*32; idx += 256) {
        int i = idx >> 5, d = idx & 31;
        Vsm[i][d] = g_V[((size_t)bh*LL + l0 + i)*HD + d];
    }
    __syncthreads();
    for (int idx = tid; idx < 32*128; idx += 256) {
        int d = idx >> 7, i = idx & 127;
        float v = Vsm[i][d];
        __half hi = __float2half_rn(v);
        __half lo = __float2half_rn(v - __half2float(hi));
        g_VT16[((size_t)bh*64 + d)*LL + l0 + i]      = hi;
        g_VT16[((size_t)bh*64 + 32 + d)*LL + l0 + i] = lo;
    }
}

// ---------------- kernel 2: prior tables via prefix sum ----------------------
__global__ __launch_bounds__(256) void prior_kernel(const float* __restrict__ u)
{
    __shared__ float Es[LL];
    __shared__ float Ps[LL];
    __shared__ float part[256];
    const int h = blockIdx.x, tid = threadIdx.x;
    float uv = u[h];
    float cc = 0.5f / (uv*uv + 1e-6f);
    #pragma unroll
    for (int j = 0; j < 8; j++) {
        int d = tid + j*256;
        float fd = (float)d;
        float e = expf(-(fd*fd)*cc);
        Es[d] = e;
        g_E[h*LL + d] = e;
    }
    __syncthreads();
    float s = 0.f;
    #pragma unroll
    for (int i = 0; i < 8; i++) s += Es[tid*8 + i];
    part[tid] = s;
    __syncthreads();
    if (tid == 0) {
        float run = 0.f;
        for (int i = 0; i < 256; i++) { run += part[i]; part[i] = run; }
    }
    __syncthreads();
    float run = (tid == 0) ? 0.f : part[tid-1];
    #pragma unroll
    for (int i = 0; i < 8; i++) {
        run += Es[tid*8 + i];
        Ps[tid*8 + i] = run;
    }
    __syncthreads();
    float e0 = Es[0];
    #pragma unroll
    for (int j = 0; j < 8; j++) {
        int q = tid + j*256;
        g_rs[h*LL + q] = Ps[q] + Ps[LL-1-q] - e0;
    }
}

// ---------------- kernel 3: FUSED scores+softmax+disc+AV via mma + ldmatrix ---
#define SMF_R2   32960
#define SMF_ES   49600
#define SMF_QST  51648
#define SMF_IRS  52176
#define SMF_TOT  52192
#define SMF_BYTES (SMF_TOT*4)

__global__ __launch_bounds__(512,1) void attn_fused_kernel()
{
    extern __shared__ float sm[];
    float*    Srow = sm;
    uint32_t* PU   = (uint32_t*)sm;
    uint32_t* R2   = (uint32_t*)(sm + SMF_R2);
    float*    Es   = sm + SMF_ES;
    float*    Op   = sm + SMF_ES;
    uint32_t* Qst  = (uint32_t*)(sm + SMF_QST);
    float*    irs  = sm + SMF_IRS;

    const uint32_t sb   = smem_u32(sm);
    const uint32_t sbR2 = sb + SMF_R2*4;

    const int tid = threadIdx.x, wid = tid >> 5, lane = tid & 31;
    const int gr = lane >> 2, kp = lane & 3;
    const int qt = blockIdx.x, bh = blockIdx.y;
    const int b = bh >> 3, h = bh & 7, q0 = qt * QT;

    {
        int r = tid >> 5, c = tid & 31;
        Qst[r*33 + c] = ((const uint32_t*)g_Q16)[((size_t)bh*LL + q0 + r)*32 + c];
    }
    for (int i = tid; i < LL; i += 512) Es[i] = g_E[h*LL + i];
    if (tid < QT) irs[tid] = 1.0f / (g_rs[h*LL + q0 + tid] + 1e-6f);
    __syncthreads();

    uint32_t qa[2][2][4];
    #pragma unroll
    for (int p = 0; p < 2; p++){
        int base = p*16;
        #pragma unroll
        for (int s = 0; s < 2; s++){
            qa[p][s][0] = Qst[ gr    *33 + base + kp     + 8*s];
            qa[p][s][1] = Qst[(gr+8) *33 + base + kp     + 8*s];
            qa[p][s][2] = Qst[ gr    *33 + base + kp + 4 + 8*s];
            qa[p][s][3] = Qst[(gr+8) *33 + base + kp + 4 + 8*s];
        }
    }

    // ---- phase 1: scores, 8 chunks of 256 keys, prefetch + ldmatrix ---------
    {
        const uint4* Gk4 = (const uint4*)g_K16;
        const int key  = tid >> 2,          q4  = tid & 3;
        const int key1 = (tid + 512) >> 2,  q41 = (tid + 512) & 3;
        uint4 pk[4];
        {
            size_t r0 = (size_t)bh*LL + key;
            size_t r1 = (size_t)bh*LL + key1;
            pk[0] = Gk4[r0*8 + q4];  pk[1] = Gk4[r0*8 + 4 + q4];
            pk[2] = Gk4[r1*8 + q41]; pk[3] = Gk4[r1*8 + 4 + q41];
        }
        for (int kc = 0; kc < 8; kc++) {
            __syncthreads();
            *(uint4*)(R2 + key *20 + q4 *4)        = pk[0];
            *(uint4*)(R2 + 5120 + key *20 + q4 *4) = pk[1];
            *(uint4*)(R2 + key1*20 + q41*4)        = pk[2];
            *(uint4*)(R2 + 5120 + key1*20 + q41*4) = pk[3];
            __syncthreads();
            if (kc < 7) {
                size_t r0 = (size_t)bh*LL + (kc+1)*256 + key;
                size_t r1 = (size_t)bh*LL + (kc+1)*256 + key1;
                pk[0] = Gk4[r0*8 + q4];  pk[1] = Gk4[r0*8 + 4 + q4];
                pk[2] = Gk4[r1*8 + q41]; pk[3] = Gk4[r1*8 + 4 + q41];
            }
            #pragma unroll
            for (int t = 0; t < 2; t++) {
                int nt = wid*2 + t;
                int n0 = nt*8;
                // B fragments via ldmatrix: rows = keys (pitch 80B), 4 matrices
                // cover k-steps s=0,1 (b0,b1 each)
                uint32_t baddr = sbR2 + (uint32_t)(n0 + (lane & 7))*80
                               + (uint32_t)((lane >> 3) & 3)*16;
                uint32_t bfh[4], bfl[4];
                ldmx4(bfh, baddr);
                ldmx4(bfl, baddr + 5120*4);
                float c[4] = {0.f,0.f,0.f,0.f};
                mma_bf16(c, qa[0][0], bfh[0], bfh[1]);
                mma_bf16(c, qa[0][0], bfl[0], bfl[1]);
                mma_bf16(c, qa[1][0], bfh[0], bfh[1]);
                mma_bf16(c, qa[0][1], bfh[2], bfh[3]);
                mma_bf16(c, qa[0][1], bfl[2], bfl[3]);
                mma_bf16(c, qa[1][1], bfh[2], bfh[3]);
                int col = kc*256 + n0 + kp*2;
                *(float2*)&Srow[ gr   *SPITCH + col] = make_float2(c[0], c[1]);
                *(float2*)&Srow[(gr+8)*SPITCH + col] = make_float2(c[2], c[3]);
            }
        }
    }
    __syncthreads();

    // ---- phase 2: softmax (float4 passes), in-place normalized f16 ----------
    {
        float* R = Srow + wid*SPITCH;
        const float4* R4 = (const float4*)R;
        float4* W4 = (float4*)R;
        float m = -3.4e38f;
        #pragma unroll
        for (int i = 0; i < 16; i++) {
            float4 v = R4[i*32 + lane];
            m = fmaxf(m, fmaxf(fmaxf(v.x, v.y), fmaxf(v.z, v.w)));
        }
        m = warpMax(m);
        float s = 0.f;
        #pragma unroll
        for (int i = 0; i < 16; i++) {
            float4 v = R4[i*32 + lane];
            v.x = __expf(v.x - m); v.y = __expf(v.y - m);
            v.z = __expf(v.z - m); v.w = __expf(v.w - m);
            s += v.x + v.y + v.z + v.w;
            W4[i*32 + lane] = v;
        }
        s = warpSum(s);
        float iv = 1.0f / s;
        uint2* W2 = (uint2*)R;
        #pragma unroll
        for (int i = 0; i < 16; i++) {
            float4 v = R4[i*32 + lane];
            __syncwarp();
            __half2 p0 = __floats2half2_rn(v.x*iv, v.y*iv);
            __half2 p1 = __floats2half2_rn(v.z*iv, v.w*iv);
            uint2 o;
            o.x = *(const uint32_t*)&p0;
            o.y = *(const uint32_t*)&p1;
            W2[i*32 + lane] = o;
        }
    }
    __syncthreads();

    // prefetch V chunk 0 (overlaps with phase 3)
    const uint4* Gv4 = (const uint4*)g_VT16;
    uint4 pv[8];
    #pragma unroll
    for (int j = 0; j < 4; j++) {
        int u2 = tid + j*512;
        int d = u2 >> 6, p4 = u2 & 63;
        pv[j*2]   = Gv4[((size_t)bh*64 + d)*256      + p4];
        pv[j*2+1] = Gv4[((size_t)bh*64 + 32 + d)*256 + p4];
    }

    // ---- phase 3: discrepancy partials (half2 reads, float2 stores) ---------
    {
        size_t pbase = (((size_t)(b*HH + h))*128 + qt) * LL;
        #pragma unroll
        for (int t = 0; t < 2; t++) {
            int k2 = tid + t*512;
            int k  = k2*2;
            float2 acc = make_float2(0.f, 0.f);
            #pragma unroll
            for (int q = 0; q < QT; q++) {
                uint32_t pa = PU[q*SPITCH + k2];
                __half2 h2 = *(const __half2*)&pa;
                float2 af = __half22float2(h2);
                float pr0 = Es[abs(q0 + q - k)]     * irs[q];
                float pr1 = Es[abs(q0 + q - k - 1)] * irs[q];
                acc.x += fabsf(af.x - pr0);
                acc.y += fabsf(af.y - pr1);
            }
            *(float2*)&g_dpart[pbase + k] = acc;
        }
    }

    // ---- phase 4: O = P @ V via mma.f16 + ldmatrix, register-prefetched ------
    {
        const int nt = wid & 3, seg = wid >> 2;
        uint32_t* Vhi = R2;
        uint32_t* Vlo = R2 + 8320;
        const uint32_t sbVhi = sbR2;
        const uint32_t sbVlo = sbR2 + 8320*4;
        float c[4] = {0.f,0.f,0.f,0.f};

        // ldmatrix lane addressing (constant parts)
        const int aq   = (lane & 7) + ((lane >> 3) & 1)*8;      // P row
        const int akof = (lane >> 4)*16;                        // byte offset in k
        const int bl8  = lane & 15;                             // x2 lanes
        const int bnrow = nt*8 + (bl8 & 7);
        const int bkof  = ((bl8 >> 3) & 1)*16;

        for (int ch = 0; ch < 4; ch++) {
            __syncthreads();
            #pragma unroll
            for (int j = 0; j < 4; j++) {
                int u2 = tid + j*512;
                int d = u2 >> 6, p4 = u2 & 63;
                *(uint4*)(Vhi + d*260 + p4*4) = pv[j*2];
                *(uint4*)(Vlo + d*260 + p4*4) = pv[j*2+1];
            }
            __syncthreads();
            if (ch < 3) {
                #pragma unroll
                for (int j = 0; j < 4; j++) {
                    int u2 = tid + j*512;
                    int d = u2 >> 6, p4 = u2 & 63;
                    pv[j*2]   = Gv4[((size_t)bh*64 + d)*256      + (ch+1)*64 + p4];
                    pv[j*2+1] = Gv4[((size_t)bh*64 + 32 + d)*256 + (ch+1)*64 + p4];
                }
            }
            #pragma unroll
            for (int ks = 0; ks < 8; ks++) {
                int kbytes = (ch*256 + seg*64 + ks*8)*4;     // P k-offset (bytes)
                int vbytes = (seg*64 + ks*8)*4;              // V k-offset (bytes)
                uint32_t af[4], bfh[2], bfl[2];
                ldmx4(af, sb + (uint32_t)aq*(SPITCH*4) + kbytes + akof);
                ldmx2(bfh, sbVhi + (uint32_t)bnrow*1040 + vbytes + bkof);
                ldmx2(bfl, sbVlo + (uint32_t)bnrow*1040 + vbytes + bkof);
                mma_f16(c, af, bfh[0], bfh[1]);
                mma_f16(c, af, bfl[0], bfl[1]);
            }
        }
        __syncthreads();
        int dcol = nt*8 + kp*2;
        Op[seg*512 +  gr   *32 + dcol]     = c[0];
        Op[seg*512 +  gr   *32 + dcol + 1] = c[1];
        Op[seg*512 + (gr+8)*32 + dcol]     = c[2];
        Op[seg*512 + (gr+8)*32 + dcol + 1] = c[3];
    }
    __syncthreads();
    {
        int q = tid >> 5, d = tid & 31;
        float s = Op[q*32 + d] + Op[512 + q*32 + d]
                + Op[1024 + q*32 + d] + Op[1536 + q*32 + d];
        g_O[((size_t)bh*LL + q0 + q)*HD + d] = s;
    }
}

// ---------------- kernel 4: discrepancy reduce (2-stage) ----------------------
__global__ void disc_reduce1_kernel()
{
    int k = blockIdx.x*256 + threadIdx.x;
    int seg = blockIdx.y;
    int b = k >> 11, kk = k & (LL-1);
    const float* base = g_dpart + (size_t)b*HH*128*LL + kk;
    float s = 0.f;
    #pragma unroll 8
    for (int p = seg*64; p < seg*64 + 64; p++) s += base[(size_t)p*LL];
    g_dpart2[seg*BB*LL + k] = s;
}
__global__ void disc_reduce2_kernel(float* __restrict__ dout)
{
    int idx = blockIdx.x*256 + threadIdx.x;
    float s = 0.f;
    #pragma unroll
    for (int seg = 0; seg < 16; seg++) s += g_dpart2[seg*BB*LL + idx];
    dout[idx] = s * (1.0f/(HH*(float)LL));
}

// ---------------- kernel 5: out projection via mma ---------------------------
__global__ __launch_bounds__(256) void outproj_mma_kernel(
    const float* __restrict__ Wo, const float* __restrict__ bo,
    float* __restrict__ out)
{
    extern __shared__ uint32_t usm[];
    uint32_t* Xh = usm;
    uint32_t* Xl = usm + LK_XL;
    uint32_t* Wh = usm + LK_WH;
    uint32_t* Wl = usm + LK_WL;

    const int m0 = blockIdx.y*128, n0 = blockIdx.x*64;
    const int tid = threadIdx.x, wid = tid>>5, lane = tid&31;
    const int gr = lane>>2, kp = lane&3;

    float c[8][4] = {};
    for (int kc = 0; kc < 4; kc++) {
        __syncthreads();
        #pragma unroll
        for (int j = 0; j < 16; j++) {
            int u2 = tid + j*256;
            int r = u2 >> 5, cc = u2 & 31;
            int m = m0 + r;
            int b = m >> 11, l = m & (LL-1);
            int k = kc*64 + cc*2;
            int hh = k >> 5, d = k & 31;
            float2 v = *(const float2*)&g_O[(((size_t)(b*HH + hh))*LL + l)*HD + d];
            __nv_bfloat162 hb = __floats2bfloat162_rn(v.x, v.y);
            __nv_bfloat162 lb = __floats2bfloat162_rn(
                v.x - __bfloat162float(hb.x), v.y - __bfloat162float(hb.y));
            Xh[r*33 + cc] = *(const uint32_t*)&hb;
            Xl[r*33 + cc] = *(const uint32_t*)&lb;
        }
        #pragma unroll
        for (int j = 0; j < 8; j++) {
            int u2 = tid + j*256;
            int r = u2 >> 5, cc = u2 & 31;
            float2 v = *(const float2*)&Wo[(size_t)(n0+r)*DD + kc*64 + cc*2];
            __nv_bfloat162 hb = __floats2bfloat162_rn(v.x, v.y);
            __nv_bfloat162 lb = __floats2bfloat162_rn(
                v.x - __bfloat162float(hb.x), v.y - __bfloat162float(hb.y));
            Wh[r*33 + cc] = *(const uint32_t*)&hb;
            Wl[r*33 + cc] = *(const uint32_t*)&lb;
        }
        __syncthreads();
        #pragma unroll
        for (int s = 0; s < 4; s++) {
            const int mb = wid*16;
            uint32_t ah[4], al[4];
            ah[0] = Xh[(mb+gr  )*33 + s*8 + kp];
            ah[1] = Xh[(mb+gr+8)*33 + s*8 + kp];
            ah[2] = Xh[(mb+gr  )*33 + s*8 + kp + 4];
            ah[3] = Xh[(mb+gr+8)*33 + s*8 + kp + 4];
            al[0] = Xl[(mb+gr  )*33 + s*8 + kp];
            al[1] = Xl[(mb+gr+8)*33 + s*8 + kp];
            al[2] = Xl[(mb+gr  )*33 + s*8 + kp + 4];
            al[3] = Xl[(mb+gr+8)*33 + s*8 + kp + 4];
            #pragma unroll
            for (int nt = 0; nt < 8; nt++) {
                uint32_t bh0 = Wh[(nt*8+gr)*33 + s*8 + kp];
                uint32_t bh1 = Wh[(nt*8+gr)*33 + s*8 + kp + 4];
                uint32_t bl0 = Wl[(nt*8+gr)*33 + s*8 + kp];
                uint32_t bl1 = Wl[(nt*8+gr)*33 + s*8 + kp + 4];
                mma_bf16(c[nt], ah, bh0, bh1);
                mma_bf16(c[nt], ah, bl0, bl1);
                mma_bf16(c[nt], al, bh0, bh1);
            }
        }
    }
    #pragma unroll
    for (int nt = 0; nt < 8; nt++) {
        #pragma unroll
        for (int hf = 0; hf < 2; hf++) {
            int m = m0 + wid*16 + gr + hf*8;
            int n = n0 + nt*8 + kp*2;
            float2 o;
            o.x = c[nt][hf*2]     + bo[n];
            o.y = c[nt][hf*2 + 1] + bo[n+1];
            *(float2*)&out[(size_t)m*DD + n] = o;
        }
    }
}

// ---------------- launch --------------------------------------------------------
extern "C" void kernel_launch(void* const* d_in, const int* in_sizes, int n_in,
                              void* d_out, int out_size)
{
    const float* x  = (const float*)d_in[0];
    const float* Wq = (const float*)d_in[1];
    const float* bq = (const float*)d_in[2];
    const float* Wk = (const float*)d_in[3];
    const float* bk = (const float*)d_in[4];
    const float* Wv = (const float*)d_in[5];
    const float* bv = (const float*)d_in[6];
    const float* u  = (const float*)d_in[7];
    const float* Wo = (const float*)d_in[8];
    const float* bo = (const float*)d_in[9];
    float* out = (float*)d_out;

    cudaFuncSetAttribute(attn_fused_kernel,
                         cudaFuncAttributeMaxDynamicSharedMemorySize, SMF_BYTES);
    cudaFuncSetAttribute(qkv_mma_kernel,
                         cudaFuncAttributeMaxDynamicSharedMemorySize, LK_TOT*4);
    cudaFuncSetAttribute(outproj_mma_kernel,
                         cudaFuncAttributeMaxDynamicSharedMemorySize, LK_TOT*4);

    qkv_mma_kernel<<<dim3(DD/64, (BB*LL)/128, 3), 256, LK_TOT*4>>>(
        x, Wq, bq, Wk, bk, Wv, bv);
    vt_kernel<<<dim3(BH, LL/128), 256>>>();
    prior_kernel<<<HH, 256>>>(u);
    attn_fused_kernel<<<dim3(LL/QT, BH), 512, SMF_BYTES>>>();
    disc_reduce1_kernel<<<dim3((BB*LL)/256, 16), 256>>>();
    disc_reduce2_kernel<<<(BB*LL)/256, 256>>>(out + (size_t)BB*LL*DD);
    outproj_mma_kernel<<<dim3(DD/64, (BB*LL)/128), 256, LK_TOT*4>>>(Wo, bo, out);
}

// round 13
// speedup vs baseline: 1.3309x; 1.2867x over previous
#include <cuda_runtime.h>
#include <cuda_bf16.h>
#include <cuda_fp16.h>
#include <math.h>
#include <stdint.h>

#define BB 2
#define LL 2048
#define DD 256
#define HH 8
#define HD 32
#define BH (BB*HH)
#define QT 16
#define PH 1036        // P strip pitch in u32 (half2 pairs); 1036*4 % 16 == 0, slot stride 3

// ---------------- scratch (device globals; no allocation allowed) ----------
__device__ float         g_V  [(size_t)BH*LL*HD];
__device__ float         g_O  [(size_t)BH*LL*HD];
__device__ __nv_bfloat16 g_Q16[(size_t)BH*LL*64];    // rows [Qhi d0..31 | Qlo d0..31] (scaled)
__device__ __nv_bfloat16 g_K16[(size_t)BH*LL*64];    // rows [Khi | Klo]
__device__ __half        g_VT16[(size_t)BH*64*LL];   // [bh][hi d / 32+lo d][l]
__device__ float         g_E  [HH*LL];
__device__ float         g_rs [HH*LL];
__device__ float         g_dpart[(size_t)BB*HH*128*LL];
__device__ float         g_dpart2[16*BB*LL];

// ---------------- helpers ----------------------------------------------------
__device__ __forceinline__ uint32_t smem_u32(const void* p){
    uint32_t a;
    asm("{ .reg .u64 t; cvta.to.shared.u64 t, %1; cvt.u32.u64 %0, t; }" : "=r"(a) : "l"(p));
    return a;
}
__device__ __forceinline__ void mma_bf16(float* c, const uint32_t* a,
                                         uint32_t b0, uint32_t b1){
    asm volatile(
        "mma.sync.aligned.m16n8k16.row.col.f32.bf16.bf16.f32 "
        "{%0,%1,%2,%3}, {%4,%5,%6,%7}, {%8,%9}, {%0,%1,%2,%3};"
        : "+f"(c[0]), "+f"(c[1]), "+f"(c[2]), "+f"(c[3])
        : "r"(a[0]), "r"(a[1]), "r"(a[2]), "r"(a[3]), "r"(b0), "r"(b1));
}
__device__ __forceinline__ void mma_f16(float* c, const uint32_t* a,
                                        uint32_t b0, uint32_t b1){
    asm volatile(
        "mma.sync.aligned.m16n8k16.row.col.f32.f16.f16.f32 "
        "{%0,%1,%2,%3}, {%4,%5,%6,%7}, {%8,%9}, {%0,%1,%2,%3};"
        : "+f"(c[0]), "+f"(c[1]), "+f"(c[2]), "+f"(c[3])
        : "r"(a[0]), "r"(a[1]), "r"(a[2]), "r"(a[3]), "r"(b0), "r"(b1));
}
__device__ __forceinline__ void ldmx4(uint32_t* r, uint32_t addr){
    asm volatile("ldmatrix.sync.aligned.m8n8.x4.shared.b16 {%0,%1,%2,%3}, [%4];"
        : "=r"(r[0]),"=r"(r[1]),"=r"(r[2]),"=r"(r[3]) : "r"(addr));
}
__device__ __forceinline__ void ldmx2(uint32_t* r, uint32_t addr){
    asm volatile("ldmatrix.sync.aligned.m8n8.x2.shared.b16 {%0,%1}, [%2];"
        : "=r"(r[0]),"=r"(r[1]) : "r"(addr));
}

// ---------------- kernel 1: QKV projection via mma (bf16 3-product split) ----
#define LK_XL (128*33)
#define LK_WH (2*128*33)
#define LK_WL (2*128*33 + 64*33)
#define LK_TOT (2*128*33 + 2*64*33)

__global__ __launch_bounds__(256) void qkv_mma_kernel(
    const float* __restrict__ x,
    const float* __restrict__ Wq, const float* __restrict__ bq,
    const float* __restrict__ Wk, const float* __restrict__ bk,
    const float* __restrict__ Wv, const float* __restrict__ bv)
{
    extern __shared__ uint32_t usm[];
    uint32_t* Xh = usm;
    uint32_t* Xl = usm + LK_XL;
    uint32_t* Wh = usm + LK_WH;
    uint32_t* Wl = usm + LK_WL;

    const float* Wm; const float* bm;
    if (blockIdx.z == 0)      { Wm=Wq; bm=bq; }
    else if (blockIdx.z == 1) { Wm=Wk; bm=bk; }
    else                      { Wm=Wv; bm=bv; }

    const int m0 = blockIdx.y*128, n0 = blockIdx.x*64;
    const int tid = threadIdx.x, wid = tid>>5, lane = tid&31;
    const int gr = lane>>2, kp = lane&3;

    float c[8][4] = {};
    for (int kc = 0; kc < 4; kc++) {
        __syncthreads();
        #pragma unroll
        for (int j = 0; j < 16; j++) {
            int u2 = tid + j*256;
            int r = u2 >> 5, cc = u2 & 31;
            float2 v = *(const float2*)&x[(size_t)(m0+r)*DD + kc*64 + cc*2];
            __nv_bfloat162 hb = __floats2bfloat162_rn(v.x, v.y);
            __nv_bfloat162 lb = __floats2bfloat162_rn(
                v.x - __bfloat162float(hb.x), v.y - __bfloat162float(hb.y));
            Xh[r*33 + cc] = *(const uint32_t*)&hb;
            Xl[r*33 + cc] = *(const uint32_t*)&lb;
        }
        #pragma unroll
        for (int j = 0; j < 8; j++) {
            int u2 = tid + j*256;
            int r = u2 >> 5, cc = u2 & 31;
            float2 v = *(const float2*)&Wm[(size_t)(n0+r)*DD + kc*64 + cc*2];
            __nv_bfloat162 hb = __floats2bfloat162_rn(v.x, v.y);
            __nv_bfloat162 lb = __floats2bfloat162_rn(
                v.x - __bfloat162float(hb.x), v.y - __bfloat162float(hb.y));
            Wh[r*33 + cc] = *(const uint32_t*)&hb;
            Wl[r*33 + cc] = *(const uint32_t*)&lb;
        }
        __syncthreads();
        #pragma unroll
        for (int s = 0; s < 4; s++) {
            const int mb = wid*16;
            uint32_t ah[4], al[4];
            ah[0] = Xh[(mb+gr  )*33 + s*8 + kp];
            ah[1] = Xh[(mb+gr+8)*33 + s*8 + kp];
            ah[2] = Xh[(mb+gr  )*33 + s*8 + kp + 4];
            ah[3] = Xh[(mb+gr+8)*33 + s*8 + kp + 4];
            al[0] = Xl[(mb+gr  )*33 + s*8 + kp];
            al[1] = Xl[(mb+gr+8)*33 + s*8 + kp];
            al[2] = Xl[(mb+gr  )*33 + s*8 + kp + 4];
            al[3] = Xl[(mb+gr+8)*33 + s*8 + kp + 4];
            #pragma unroll
            for (int nt = 0; nt < 8; nt++) {
                uint32_t bh0 = Wh[(nt*8+gr)*33 + s*8 + kp];
                uint32_t bh1 = Wh[(nt*8+gr)*33 + s*8 + kp + 4];
                uint32_t bl0 = Wl[(nt*8+gr)*33 + s*8 + kp];
                uint32_t bl1 = Wl[(nt*8+gr)*33 + s*8 + kp + 4];
                mma_bf16(c[nt], ah, bh0, bh1);
                mma_bf16(c[nt], ah, bl0, bl1);
                mma_bf16(c[nt], al, bh0, bh1);
            }
        }
    }
    const float SCALE = 0.17677669529663687f;
    #pragma unroll
    for (int nt = 0; nt < 8; nt++) {
        #pragma unroll
        for (int hf = 0; hf < 2; hf++) {
            int m = m0 + wid*16 + gr + hf*8;
            int b = m >> 11, l = m & (LL-1);
            #pragma unroll
            for (int e = 0; e < 2; e++) {
                int n = n0 + nt*8 + kp*2 + e;
                float v = c[nt][hf*2 + e] + bm[n];
                int h = n >> 5, d = n & 31;
                size_t row = (size_t)(b*HH + h)*LL + l;
                if (blockIdx.z == 0) {
                    float sv = v * SCALE;
                    __nv_bfloat16 hi = __float2bfloat16(sv);
                    g_Q16[row*64 + d]      = hi;
                    g_Q16[row*64 + 32 + d] = __float2bfloat16(sv - __bfloat162float(hi));
                } else if (blockIdx.z == 1) {
                    __nv_bfloat16 hi = __float2bfloat16(v);
                    g_K16[row*64 + d]      = hi;
                    g_K16[row*64 + 32 + d] = __float2bfloat16(v - __bfloat162float(hi));
                } else {
                    g_V[row*HD + d] = v;
                }
            }
        }
    }
}

// ---------------- kernel 1b: V transpose + f16 hi/lo -------------------------
__global__ __launch_bounds__(256) void vt_kernel()
{
    __shared__ float Vsm[128][33];
    const int bh = blockIdx.x, l0 = blockIdx.y*128;
    const int tid = threadIdx.x;
    for (int idx = tid; idx < 128*32; idx += 256) {
        int i = idx >> 5, d = idx & 31;
        Vsm[i][d] = g_V[((size_t)bh*LL + l0 + i)*HD + d];
    }
    __syncthreads();
    for (int idx = tid; idx < 32*128; idx += 256) {
        int d = idx >> 7, i = idx & 127;
        float v = Vsm[i][d];
        __half hi = __float2half_rn(v);
        __half lo = __float2half_rn(v - __half2float(hi));
        g_VT16[((size_t)bh*64 + d)*LL + l0 + i]      = hi;
        g_VT16[((size_t)bh*64 + 32 + d)*LL + l0 + i] = lo;
    }
}

// ---------------- kernel 2: prior tables via prefix sum ----------------------
__global__ __launch_bounds__(256) void prior_kernel(const float* __restrict__ u)
{
    __shared__ float Es[LL];
    __shared__ float Ps[LL];
    __shared__ float part[256];
    const int h = blockIdx.x, tid = threadIdx.x;
    float uv = u[h];
    float cc = 0.5f / (uv*uv + 1e-6f);
    #pragma unroll
    for (int j = 0; j < 8; j++) {
        int d = tid + j*256;
        float fd = (float)d;
        float e = expf(-(fd*fd)*cc);
        Es[d] = e;
        g_E[h*LL + d] = e;
    }
    __syncthreads();
    float s = 0.f;
    #pragma unroll
    for (int i = 0; i < 8; i++) s += Es[tid*8 + i];
    part[tid] = s;
    __syncthreads();
    if (tid == 0) {
        float run = 0.f;
        for (int i = 0; i < 256; i++) { run += part[i]; part[i] = run; }
    }
    __syncthreads();
    float run = (tid == 0) ? 0.f : part[tid-1];
    #pragma unroll
    for (int i = 0; i < 8; i++) {
        run += Es[tid*8 + i];
        Ps[tid*8 + i] = run;
    }
    __syncthreads();
    float e0 = Es[0];
    #pragma unroll
    for (int j = 0; j < 8; j++) {
        int q = tid + j*256;
        g_rs[h*LL + q] = Ps[q] + Ps[LL-1-q] - e0;
    }
}

// ---------------- kernel 3: FUSED scores(exp)+disc+AV, 2 blocks/SM -----------
// SMEM (u32 units):
//  P strip  [0, 16576)       16 rows x PH (e as half2 pairs)
//  Kst      [16576, 21696)   K chunk (128 keys x 20 hi | +2560 lo)
//                            reused as V chunk (32 d x 68 hi | +2176 lo)
//  Es       [21696, 23744)   prior table (reused as Op 4x16x32 in epilogue)
//  Qst      [23744, 24272)
//  red      [24272, 24528)
//  inv      [24528, 24544)
//  irs      [24544, 24560)
#define SMF_P    0
#define SMF_KST  16576
#define SMF_ES   21696
#define SMF_QST  23744
#define SMF_RED  24272
#define SMF_INV  24528
#define SMF_IRS  24544
#define SMF_TOT  24560
#define SMF_BYTES (SMF_TOT*4)

__global__ __launch_bounds__(512,2) void attn_fused_kernel()
{
    extern __shared__ uint32_t usm2[];
    uint32_t* PU  = usm2 + SMF_P;
    uint32_t* Kst = usm2 + SMF_KST;
    float*    Es  = (float*)(usm2 + SMF_ES);
    float*    Op  = (float*)(usm2 + SMF_ES);     // overlay, used after disc
    uint32_t* Qst = usm2 + SMF_QST;
    float*    red = (float*)(usm2 + SMF_RED);
    float*    inv = (float*)(usm2 + SMF_INV);
    float*    irs = (float*)(usm2 + SMF_IRS);

    const uint32_t sb    = smem_u32(usm2);
    const uint32_t sbP   = sb;
    const uint32_t sbKst = sb + SMF_KST*4;

    const int tid = threadIdx.x, wid = tid >> 5, lane = tid & 31;
    const int gr = lane >> 2, kp = lane & 3;
    const int qt = blockIdx.x, bh = blockIdx.y;
    const int b = bh >> 3, h = bh & 7, q0 = qt * QT;

    // ---- phase 0 -------------------------------------------------------------
    {
        int r = tid >> 5, c = tid & 31;
        Qst[r*33 + c] = ((const uint32_t*)g_Q16)[((size_t)bh*LL + q0 + r)*32 + c];
    }
    for (int i = tid; i < LL; i += 512) Es[i] = g_E[h*LL + i];
    if (tid < QT) irs[tid] = 1.0f / (g_rs[h*LL + q0 + tid] + 1e-6f);
    __syncthreads();

    uint32_t qa[2][2][4];
    #pragma unroll
    for (int p = 0; p < 2; p++){
        int base = p*16;
        #pragma unroll
        for (int s = 0; s < 2; s++){
            qa[p][s][0] = Qst[ gr    *33 + base + kp     + 8*s];
            qa[p][s][1] = Qst[(gr+8) *33 + base + kp     + 8*s];
            qa[p][s][2] = Qst[ gr    *33 + base + kp + 4 + 8*s];
            qa[p][s][3] = Qst[(gr+8) *33 + base + kp + 4 + 8*s];
        }
    }

    // ---- phase 1: scores -> e (f16), row sums; 16 chunks of 128 keys ----------
    float s0 = 0.f, s1 = 0.f;
    {
        const uint4* Gk4 = (const uint4*)g_K16;
        const size_t kbase = (size_t)bh*LL*8;
        const int g0 = tid, g1 = tid + 512;
        const int dst0 = (g0>>3)*20 + (g0&3)*4 + ((g0>>2)&1)*2560;
        const int dst1 = (g1>>3)*20 + (g1&3)*4 + ((g1>>2)&1)*2560;
        uint4 pk0 = Gk4[kbase + g0];
        uint4 pk1 = Gk4[kbase + g1];
        const uint32_t baddr = sbKst + (uint32_t)(wid*8 + (lane&7))*80
                             + (uint32_t)((lane>>3)&3)*16;

        for (int kc = 0; kc < 16; kc++) {
            __syncthreads();
            *(uint4*)(Kst + dst0) = pk0;
            *(uint4*)(Kst + dst1) = pk1;
            __syncthreads();
            if (kc < 15) {
                pk0 = Gk4[kbase + (kc+1)*1024 + g0];
                pk1 = Gk4[kbase + (kc+1)*1024 + g1];
            }
            uint32_t bfh[4], bfl[4];
            ldmx4(bfh, baddr);
            ldmx4(bfl, baddr + 2560*4);
            float c[4] = {0.f,0.f,0.f,0.f};
            mma_bf16(c, qa[0][0], bfh[0], bfh[1]);
            mma_bf16(c, qa[0][0], bfl[0], bfl[1]);
            mma_bf16(c, qa[1][0], bfh[0], bfh[1]);
            mma_bf16(c, qa[0][1], bfh[2], bfh[3]);
            mma_bf16(c, qa[0][1], bfl[2], bfl[3]);
            mma_bf16(c, qa[1][1], bfh[2], bfh[3]);
            float e0 = __expf(c[0]), e1 = __expf(c[1]);
            float e2 = __expf(c[2]), e3 = __expf(c[3]);
            s0 += e0 + e1;
            s1 += e2 + e3;
            __half2 h01 = __floats2half2_rn(e0, e1);
            __half2 h23 = __floats2half2_rn(e2, e3);
            int col = kc*64 + wid*4 + kp;
            PU[ gr   *PH + col] = *(const uint32_t*)&h01;
            PU[(gr+8)*PH + col] = *(const uint32_t*)&h23;
        }
    }
    // row-sum reduction
    s0 += __shfl_xor_sync(0xffffffffu, s0, 1);
    s0 += __shfl_xor_sync(0xffffffffu, s0, 2);
    s1 += __shfl_xor_sync(0xffffffffu, s1, 1);
    s1 += __shfl_xor_sync(0xffffffffu, s1, 2);
    if (kp == 0) {
        red[wid*16 + gr]     = s0;
        red[wid*16 + gr + 8] = s1;
    }
    __syncthreads();
    if (tid < QT) {
        float s = 0.f;
        #pragma unroll
        for (int w = 0; w < 16; w++) s += red[w*16 + tid];
        inv[tid] = 1.0f / s;
    }
    __syncthreads();

    // prefetch V chunk 0 (overlaps with disc)
    const uint4* Gv4 = (const uint4*)g_VT16;
    const int vd = tid >> 4, vp4 = tid & 15;
    uint4 pv0 = Gv4[((size_t)bh*64 + vd)*256 + vp4];
    uint4 pv1 = Gv4[((size_t)bh*64 + 32 + vd)*256 + vp4];

    // ---- phase 2: discrepancy partials (e*inv, half2 reads) -------------------
    {
        size_t pbase = (((size_t)(b*HH + h))*128 + qt) * LL;
        #pragma unroll
        for (int t = 0; t < 2; t++) {
            int k2 = tid + t*512;
            int k  = k2*2;
            float2 acc = make_float2(0.f, 0.f);
            #pragma unroll
            for (int q = 0; q < QT; q++) {
                uint32_t pa = PU[q*PH + k2];
                __half2 h2 = *(const __half2*)&pa;
                float2 af = __half22float2(h2);
                float ivq = inv[q];
                float pr0 = Es[abs(q0 + q - k)]     * irs[q];
                float pr1 = Es[abs(q0 + q - k - 1)] * irs[q];
                acc.x += fabsf(af.x*ivq - pr0);
                acc.y += fabsf(af.y*ivq - pr1);
            }
            *(float2*)&g_dpart[pbase + k] = acc;
        }
    }

    // ---- phase 3: O = (e @ V) * inv via mma.f16 + ldmatrix --------------------
    {
        const int nt = wid & 3, seg = wid >> 2;
        uint32_t* Vhi = Kst;
        uint32_t* Vlo = Kst + 2176;
        const uint32_t sbVhi = sbKst;
        const uint32_t sbVlo = sbKst + 2176*4;
        float c[4] = {0.f,0.f,0.f,0.f};

        const int aq   = (lane & 7) + ((lane >> 3) & 1)*8;
        const int akof = (lane >> 4)*16;
        const int bl8  = lane & 15;
        const int bnrow = nt*8 + (bl8 & 7);
        const int bkof  = ((bl8 >> 3) & 1)*16;

        for (int ch = 0; ch < 16; ch++) {
            __syncthreads();
            *(uint4*)(Vhi + vd*68 + vp4*4) = pv0;
            *(uint4*)(Vlo + vd*68 + vp4*4) = pv1;
            __syncthreads();
            if (ch < 15) {
                pv0 = Gv4[((size_t)bh*64 + vd)*256      + (ch+1)*16 + vp4];
                pv1 = Gv4[((size_t)bh*64 + 32 + vd)*256 + (ch+1)*16 + vp4];
            }
            #pragma unroll
            for (int ks = 0; ks < 2; ks++) {
                int kbytes = (ch*64 + seg*16 + ks*8)*4;
                int vbytes = (seg*16 + ks*8)*4;
                uint32_t af[4], bfh[2], bfl[2];
                ldmx4(af, sbP + (uint32_t)aq*(PH*4) + kbytes + akof);
                ldmx2(bfh, sbVhi + (uint32_t)bnrow*272 + vbytes + bkof);
                ldmx2(bfl, sbVlo + (uint32_t)bnrow*272 + vbytes + bkof);
                mma_f16(c, af, bfh[0], bfh[1]);
                mma_f16(c, af, bfl[0], bfl[1]);
            }
        }
        __syncthreads();     // Es region no longer needed -> Op
        int dcol = nt*8 + kp*2;
        Op[seg*512 +  gr   *32 + dcol]     = c[0];
        Op[seg*512 +  gr   *32 + dcol + 1] = c[1];
        Op[seg*512 + (gr+8)*32 + dcol]     = c[2];
        Op[seg*512 + (gr+8)*32 + dcol + 1] = c[3];
    }
    __syncthreads();
    {
        int q = tid >> 5, d = tid & 31;
        float s = (Op[q*32 + d] + Op[512 + q*32 + d]
                 + Op[1024 + q*32 + d] + Op[1536 + q*32 + d]) * inv[q];
        g_O[((size_t)bh*LL + q0 + q)*HD + d] = s;
    }
}

// ---------------- kernel 4: discrepancy reduce (2-stage) ----------------------
__global__ void disc_reduce1_kernel()
{
    int k = blockIdx.x*256 + threadIdx.x;
    int seg = blockIdx.y;
    int b = k >> 11, kk = k & (LL-1);
    const float* base = g_dpart + (size_t)b*HH*128*LL + kk;
    float s = 0.f;
    #pragma unroll 8
    for (int p = seg*64; p < seg*64 + 64; p++) s += base[(size_t)p*LL];
    g_dpart2[seg*BB*LL + k] = s;
}
__global__ void disc_reduce2_kernel(float* __restrict__ dout)
{
    int idx = blockIdx.x*256 + threadIdx.x;
    float s = 0.f;
    #pragma unroll
    for (int seg = 0; seg < 16; seg++) s += g_dpart2[seg*BB*LL + idx];
    dout[idx] = s * (1.0f/(HH*(float)LL));
}

// ---------------- kernel 5: out projection via mma ---------------------------
__global__ __launch_bounds__(256) void outproj_mma_kernel(
    const float* __restrict__ Wo, const float* __restrict__ bo,
    float* __restrict__ out)
{
    extern __shared__ uint32_t usm[];
    uint32_t* Xh = usm;
    uint32_t* Xl = usm + LK_XL;
    uint32_t* Wh = usm + LK_WH;
    uint32_t* Wl = usm + LK_WL;

    const int m0 = blockIdx.y*128, n0 = blockIdx.x*64;
    const int tid = threadIdx.x, wid = tid>>5, lane = tid&31;
    const int gr = lane>>2, kp = lane&3;

    float c[8][4] = {};
    for (int kc = 0; kc < 4; kc++) {
        __syncthreads();
        #pragma unroll
        for (int j = 0; j < 16; j++) {
            int u2 = tid + j*256;
            int r = u2 >> 5, cc = u2 & 31;
            int m = m0 + r;
            int b = m >> 11, l = m & (LL-1);
            int k = kc*64 + cc*2;
            int hh = k >> 5, d = k & 31;
            float2 v = *(const float2*)&g_O[(((size_t)(b*HH + hh))*LL + l)*HD + d];
            __nv_bfloat162 hb = __floats2bfloat162_rn(v.x, v.y);
            __nv_bfloat162 lb = __floats2bfloat162_rn(
                v.x - __bfloat162float(hb.x), v.y - __bfloat162float(hb.y));
            Xh[r*33 + cc] = *(const uint32_t*)&hb;
            Xl[r*33 + cc] = *(const uint32_t*)&lb;
        }
        #pragma unroll
        for (int j = 0; j < 8; j++) {
            int u2 = tid + j*256;
            int r = u2 >> 5, cc = u2 & 31;
            float2 v = *(const float2*)&Wo[(size_t)(n0+r)*DD + kc*64 + cc*2];
            __nv_bfloat162 hb = __floats2bfloat162_rn(v.x, v.y);
            __nv_bfloat162 lb = __floats2bfloat162_rn(
                v.x - __bfloat162float(hb.x), v.y - __bfloat162float(hb.y));
            Wh[r*33 + cc] = *(const uint32_t*)&hb;
            Wl[r*33 + cc] = *(const uint32_t*)&lb;
        }
        __syncthreads();
        #pragma unroll
        for (int s = 0; s < 4; s++) {
            const int mb = wid*16;
            uint32_t ah[4], al[4];
            ah[0] = Xh[(mb+gr  )*33 + s*8 + kp];
            ah[1] = Xh[(mb+gr+8)*33 + s*8 + kp];
            ah[2] = Xh[(mb+gr  )*33 + s*8 + kp + 4];
            ah[3] = Xh[(mb+gr+8)*33 + s*8 + kp + 4];
            al[0] = Xl[(mb+gr  )*33 + s*8 + kp];
            al[1] = Xl[(mb+gr+8)*33 + s*8 + kp];
            al[2] = Xl[(mb+gr  )*33 + s*8 + kp + 4];
            al[3] = Xl[(mb+gr+8)*33 + s*8 + kp + 4];
            #pragma unroll
            for (int nt = 0; nt < 8; nt++) {
                uint32_t bh0 = Wh[(nt*8+gr)*33 + s*8 + kp];
                uint32_t bh1 = Wh[(nt*8+gr)*33 + s*8 + kp + 4];
                uint32_t bl0 = Wl[(nt*8+gr)*33 + s*8 + kp];
                uint32_t bl1 = Wl[(nt*8+gr)*33 + s*8 + kp + 4];
                mma_bf16(c[nt], ah, bh0, bh1);
                mma_bf16(c[nt], ah, bl0, bl1);
                mma_bf16(c[nt], al, bh0, bh1);
            }
        }
    }
    #pragma unroll
    for (int nt = 0; nt < 8; nt++) {
        #pragma unroll
        for (int hf = 0; hf < 2; hf++) {
            int m = m0 + wid*16 + gr + hf*8;
            int n = n0 + nt*8 + kp*2;
            float2 o;
            o.x = c[nt][hf*2]     + bo[n];
            o.y = c[nt][hf*2 + 1] + bo[n+1];
            *(float2*)&out[(size_t)m*DD + n] = o;
        }
    }
}

// ---------------- launch --------------------------------------------------------
extern "C" void kernel_launch(void* const* d_in, const int* in_sizes, int n_in,
                              void* d_out, int out_size)
{
    const float* x  = (const float*)d_in[0];
    const float* Wq = (const float*)d_in[1];
    const float* bq = (const float*)d_in[2];
    const float* Wk = (const float*)d_in[3];
    const float* bk = (const float*)d_in[4];
    const float* Wv = (const float*)d_in[5];
    const float* bv = (const float*)d_in[6];
    const float* u  = (const float*)d_in[7];
    const float* Wo = (const float*)d_in[8];
    const float* bo = (const float*)d_in[9];
    float* out = (float*)d_out;

    cudaFuncSetAttribute(attn_fused_kernel,
                         cudaFuncAttributeMaxDynamicSharedMemorySize, SMF_BYTES);
    cudaFuncSetAttribute(qkv_mma_kernel,
                         cudaFuncAttributeMaxDynamicSharedMemorySize, LK_TOT*4);
    cudaFuncSetAttribute(outproj_mma_kernel,
                         cudaFuncAttributeMaxDynamicSharedMemorySize, LK_TOT*4);

    qkv_mma_kernel<<<dim3(DD/64, (BB*LL)/128, 3), 256, LK_TOT*4>>>(
        x, Wq, bq, Wk, bk, Wv, bv);
    vt_kernel<<<dim3(BH, LL/128), 256>>>();
    prior_kernel<<<HH, 256>>>(u);
    attn_fused_kernel<<<dim3(LL/QT, BH), 512, SMF_BYTES>>>();
    disc_reduce1_kernel<<<dim3((BB*LL)/256, 16), 256>>>();
    disc_reduce2_kernel<<<(BB*LL)/256, 256>>>(out + (size_t)BB*LL*DD);
    outproj_mma_kernel<<<dim3(DD/64, (BB*LL)/128), 256, LK_TOT*4>>>(Wo, bo, out);
}

// round 14
// speedup vs baseline: 1.4764x; 1.1093x over previous
#include <cuda_runtime.h>
#include <cuda_bf16.h>
#include <cuda_fp16.h>
#include <math.h>
#include <stdint.h>

#define BB 2
#define LL 2048
#define DD 256
#define HH 8
#define HD 32
#define BH (BB*HH)
#define QT 16
#define PH 1036        // P strip pitch in u32 (half2 pairs)

// ---------------- scratch (device globals; no allocation allowed) ----------
__device__ float         g_V  [(size_t)BH*LL*HD];
__device__ float         g_O  [(size_t)BH*LL*HD];
__device__ __nv_bfloat16 g_Q16[(size_t)BH*LL*64];    // rows [Qhi d0..31 | Qlo d0..31] (scaled)
__device__ __nv_bfloat16 g_K16[(size_t)BH*LL*64];    // rows [Khi | Klo]
__device__ __half        g_VT16[(size_t)BH*32*LL];   // [bh][d][l]  (single f16)
__device__ float         g_E  [HH*LL];
__device__ float         g_rs [HH*LL];
__device__ float         g_dpart[(size_t)BB*HH*128*LL];
__device__ float         g_dpart2[16*BB*LL];

// ---------------- helpers ----------------------------------------------------
__device__ __forceinline__ uint32_t smem_u32(const void* p){
    uint32_t a;
    asm("{ .reg .u64 t; cvta.to.shared.u64 t, %1; cvt.u32.u64 %0, t; }" : "=r"(a) : "l"(p));
    return a;
}
__device__ __forceinline__ void mma_bf16(float* c, const uint32_t* a,
                                         uint32_t b0, uint32_t b1){
    asm volatile(
        "mma.sync.aligned.m16n8k16.row.col.f32.bf16.bf16.f32 "
        "{%0,%1,%2,%3}, {%4,%5,%6,%7}, {%8,%9}, {%0,%1,%2,%3};"
        : "+f"(c[0]), "+f"(c[1]), "+f"(c[2]), "+f"(c[3])
        : "r"(a[0]), "r"(a[1]), "r"(a[2]), "r"(a[3]), "r"(b0), "r"(b1));
}
__device__ __forceinline__ void mma_f16(float* c, const uint32_t* a,
                                        uint32_t b0, uint32_t b1){
    asm volatile(
        "mma.sync.aligned.m16n8k16.row.col.f32.f16.f16.f32 "
        "{%0,%1,%2,%3}, {%4,%5,%6,%7}, {%8,%9}, {%0,%1,%2,%3};"
        : "+f"(c[0]), "+f"(c[1]), "+f"(c[2]), "+f"(c[3])
        : "r"(a[0]), "r"(a[1]), "r"(a[2]), "r"(a[3]), "r"(b0), "r"(b1));
}
__device__ __forceinline__ void ldmx4(uint32_t* r, uint32_t addr){
    asm volatile("ldmatrix.sync.aligned.m8n8.x4.shared.b16 {%0,%1,%2,%3}, [%4];"
        : "=r"(r[0]),"=r"(r[1]),"=r"(r[2]),"=r"(r[3]) : "r"(addr));
}
__device__ __forceinline__ void ldmx2(uint32_t* r, uint32_t addr){
    asm volatile("ldmatrix.sync.aligned.m8n8.x2.shared.b16 {%0,%1}, [%2];"
        : "=r"(r[0]),"=r"(r[1]) : "r"(addr));
}

// ---------------- kernel 1: QKV projection via mma (bf16 3-product split) ----
#define LK_XL (128*33)
#define LK_WH (2*128*33)
#define LK_WL (2*128*33 + 64*33)
#define LK_TOT (2*128*33 + 2*64*33)

__global__ __launch_bounds__(256) void qkv_mma_kernel(
    const float* __restrict__ x,
    const float* __restrict__ Wq, const float* __restrict__ bq,
    const float* __restrict__ Wk, const float* __restrict__ bk,
    const float* __restrict__ Wv, const float* __restrict__ bv)
{
    extern __shared__ uint32_t usm[];
    uint32_t* Xh = usm;
    uint32_t* Xl = usm + LK_XL;
    uint32_t* Wh = usm + LK_WH;
    uint32_t* Wl = usm + LK_WL;

    const float* Wm; const float* bm;
    if (blockIdx.z == 0)      { Wm=Wq; bm=bq; }
    else if (blockIdx.z == 1) { Wm=Wk; bm=bk; }
    else                      { Wm=Wv; bm=bv; }

    const int m0 = blockIdx.y*128, n0 = blockIdx.x*64;
    const int tid = threadIdx.x, wid = tid>>5, lane = tid&31;
    const int gr = lane>>2, kp = lane&3;

    float c[8][4] = {};
    for (int kc = 0; kc < 4; kc++) {
        __syncthreads();
        #pragma unroll
        for (int j = 0; j < 16; j++) {
            int u2 = tid + j*256;
            int r = u2 >> 5, cc = u2 & 31;
            float2 v = *(const float2*)&x[(size_t)(m0+r)*DD + kc*64 + cc*2];
            __nv_bfloat162 hb = __floats2bfloat162_rn(v.x, v.y);
            __nv_bfloat162 lb = __floats2bfloat162_rn(
                v.x - __bfloat162float(hb.x), v.y - __bfloat162float(hb.y));
            Xh[r*33 + cc] = *(const uint32_t*)&hb;
            Xl[r*33 + cc] = *(const uint32_t*)&lb;
        }
        #pragma unroll
        for (int j = 0; j < 8; j++) {
            int u2 = tid + j*256;
            int r = u2 >> 5, cc = u2 & 31;
            float2 v = *(const float2*)&Wm[(size_t)(n0+r)*DD + kc*64 + cc*2];
            __nv_bfloat162 hb = __floats2bfloat162_rn(v.x, v.y);
            __nv_bfloat162 lb = __floats2bfloat162_rn(
                v.x - __bfloat162float(hb.x), v.y - __bfloat162float(hb.y));
            Wh[r*33 + cc] = *(const uint32_t*)&hb;
            Wl[r*33 + cc] = *(const uint32_t*)&lb;
        }
        __syncthreads();
        #pragma unroll
        for (int s = 0; s < 4; s++) {
            const int mb = wid*16;
            uint32_t ah[4], al[4];
            ah[0] = Xh[(mb+gr  )*33 + s*8 + kp];
            ah[1] = Xh[(mb+gr+8)*33 + s*8 + kp];
            ah[2] = Xh[(mb+gr  )*33 + s*8 + kp + 4];
            ah[3] = Xh[(mb+gr+8)*33 + s*8 + kp + 4];
            al[0] = Xl[(mb+gr  )*33 + s*8 + kp];
            al[1] = Xl[(mb+gr+8)*33 + s*8 + kp];
            al[2] = Xl[(mb+gr  )*33 + s*8 + kp + 4];
            al[3] = Xl[(mb+gr+8)*33 + s*8 + kp + 4];
            #pragma unroll
            for (int nt = 0; nt < 8; nt++) {
                uint32_t bh0 = Wh[(nt*8+gr)*33 + s*8 + kp];
                uint32_t bh1 = Wh[(nt*8+gr)*33 + s*8 + kp + 4];
                uint32_t bl0 = Wl[(nt*8+gr)*33 + s*8 + kp];
                uint32_t bl1 = Wl[(nt*8+gr)*33 + s*8 + kp + 4];
                mma_bf16(c[nt], ah, bh0, bh1);
                mma_bf16(c[nt], ah, bl0, bl1);
                mma_bf16(c[nt], al, bh0, bh1);
            }
        }
    }
    const float SCALE = 0.17677669529663687f;
    #pragma unroll
    for (int nt = 0; nt < 8; nt++) {
        #pragma unroll
        for (int hf = 0; hf < 2; hf++) {
            int m = m0 + wid*16 + gr + hf*8;
            int b = m >> 11, l = m & (LL-1);
            #pragma unroll
            for (int e = 0; e < 2; e++) {
                int n = n0 + nt*8 + kp*2 + e;
                float v = c[nt][hf*2 + e] + bm[n];
                int h = n >> 5, d = n & 31;
                size_t row = (size_t)(b*HH + h)*LL + l;
                if (blockIdx.z == 0) {
                    float sv = v * SCALE;
                    __nv_bfloat16 hi = __float2bfloat16(sv);
                    g_Q16[row*64 + d]      = hi;
                    g_Q16[row*64 + 32 + d] = __float2bfloat16(sv - __bfloat162float(hi));
                } else if (blockIdx.z == 1) {
                    __nv_bfloat16 hi = __float2bfloat16(v);
                    g_K16[row*64 + d]      = hi;
                    g_K16[row*64 + 32 + d] = __float2bfloat16(v - __bfloat162float(hi));
                } else {
                    g_V[row*HD + d] = v;
                }
            }
        }
    }
}

// ---------------- kernel 1b: V transpose -> f16 (single) ---------------------
__global__ __launch_bounds__(256) void vt_kernel()
{
    __shared__ float Vsm[128][33];
    const int bh = blockIdx.x, l0 = blockIdx.y*128;
    const int tid = threadIdx.x;
    for (int idx = tid; idx < 128*32; idx += 256) {
        int i = idx >> 5, d = idx & 31;
        Vsm[i][d] = g_V[((size_t)bh*LL + l0 + i)*HD + d];
    }
    __syncthreads();
    for (int idx = tid; idx < 32*128; idx += 256) {
        int d = idx >> 7, i = idx & 127;
        g_VT16[((size_t)bh*32 + d)*LL + l0 + i] = __float2half_rn(Vsm[i][d]);
    }
}

// ---------------- kernel 2: prior tables via prefix sum ----------------------
__global__ __launch_bounds__(256) void prior_kernel(const float* __restrict__ u)
{
    __shared__ float Es[LL];
    __shared__ float Ps[LL];
    __shared__ float part[256];
    const int h = blockIdx.x, tid = threadIdx.x;
    float uv = u[h];
    float cc = 0.5f / (uv*uv + 1e-6f);
    #pragma unroll
    for (int j = 0; j < 8; j++) {
        int d = tid + j*256;
        float fd = (float)d;
        float e = expf(-(fd*fd)*cc);
        Es[d] = e;
        g_E[h*LL + d] = e;
    }
    __syncthreads();
    float s = 0.f;
    #pragma unroll
    for (int i = 0; i < 8; i++) s += Es[tid*8 + i];
    part[tid] = s;
    __syncthreads();
    if (tid == 0) {
        float run = 0.f;
        for (int i = 0; i < 256; i++) { run += part[i]; part[i] = run; }
    }
    __syncthreads();
    float run = (tid == 0) ? 0.f : part[tid-1];
    #pragma unroll
    for (int i = 0; i < 8; i++) {
        run += Es[tid*8 + i];
        Ps[tid*8 + i] = run;
    }
    __syncthreads();
    float e0 = Es[0];
    #pragma unroll
    for (int j = 0; j < 8; j++) {
        int q = tid + j*256;
        g_rs[h*LL + q] = Ps[q] + Ps[LL-1-q] - e0;
    }
}

// ---------------- kernel 3: FUSED scores(exp)+disc+AV, 2 blocks/SM -----------
#define SMF_P    0
#define SMF_KST  16576
#define SMF_ES   21696
#define SMF_QST  23744
#define SMF_RED  24272
#define SMF_INV  24528
#define SMF_IRS  24544
#define SMF_TOT  24560
#define SMF_BYTES (SMF_TOT*4)

__global__ __launch_bounds__(512,2) void attn_fused_kernel()
{
    extern __shared__ uint32_t usm2[];
    uint32_t* PU  = usm2 + SMF_P;
    uint32_t* Kst = usm2 + SMF_KST;
    float*    Es  = (float*)(usm2 + SMF_ES);
    float*    Op  = (float*)(usm2 + SMF_ES);     // overlay, used after disc
    uint32_t* Qst = usm2 + SMF_QST;
    float*    red = (float*)(usm2 + SMF_RED);
    float*    inv = (float*)(usm2 + SMF_INV);
    float*    irs = (float*)(usm2 + SMF_IRS);

    const uint32_t sb    = smem_u32(usm2);
    const uint32_t sbP   = sb;
    const uint32_t sbKst = sb + SMF_KST*4;

    const int tid = threadIdx.x, wid = tid >> 5, lane = tid & 31;
    const int gr = lane >> 2, kp = lane & 3;
    const int qt = blockIdx.x, bh = blockIdx.y;
    const int b = bh >> 3, h = bh & 7, q0 = qt * QT;

    // ---- phase 0 -------------------------------------------------------------
    {
        int r = tid >> 5, c = tid & 31;
        Qst[r*33 + c] = ((const uint32_t*)g_Q16)[((size_t)bh*LL + q0 + r)*32 + c];
    }
    for (int i = tid; i < LL; i += 512) Es[i] = g_E[h*LL + i];
    if (tid < QT) irs[tid] = 1.0f / (g_rs[h*LL + q0 + tid] + 1e-6f);
    __syncthreads();

    uint32_t qa[2][2][4];
    #pragma unroll
    for (int p = 0; p < 2; p++){
        int base = p*16;
        #pragma unroll
        for (int s = 0; s < 2; s++){
            qa[p][s][0] = Qst[ gr    *33 + base + kp     + 8*s];
            qa[p][s][1] = Qst[(gr+8) *33 + base + kp     + 8*s];
            qa[p][s][2] = Qst[ gr    *33 + base + kp + 4 + 8*s];
            qa[p][s][3] = Qst[(gr+8) *33 + base + kp + 4 + 8*s];
        }
    }

    // ---- phase 1: scores -> e (f16), row sums; 16 chunks of 128 keys ----------
    float s0 = 0.f, s1 = 0.f;
    {
        const uint4* Gk4 = (const uint4*)g_K16;
        const size_t kbase = (size_t)bh*LL*8;
        const int g0 = tid, g1 = tid + 512;
        const int dst0 = (g0>>3)*20 + (g0&3)*4 + ((g0>>2)&1)*2560;
        const int dst1 = (g1>>3)*20 + (g1&3)*4 + ((g1>>2)&1)*2560;
        uint4 pk0 = Gk4[kbase + g0];
        uint4 pk1 = Gk4[kbase + g1];
        const uint32_t baddr = sbKst + (uint32_t)(wid*8 + (lane&7))*80
                             + (uint32_t)((lane>>3)&3)*16;

        for (int kc = 0; kc < 16; kc++) {
            __syncthreads();
            *(uint4*)(Kst + dst0) = pk0;
            *(uint4*)(Kst + dst1) = pk1;
            __syncthreads();
            if (kc < 15) {
                pk0 = Gk4[kbase + (kc+1)*1024 + g0];
                pk1 = Gk4[kbase + (kc+1)*1024 + g1];
            }
            uint32_t bfh[4], bfl[4];
            ldmx4(bfh, baddr);
            ldmx4(bfl, baddr + 2560*4);
            float c[4] = {0.f,0.f,0.f,0.f};
            mma_bf16(c, qa[0][0], bfh[0], bfh[1]);
            mma_bf16(c, qa[0][0], bfl[0], bfl[1]);
            mma_bf16(c, qa[1][0], bfh[0], bfh[1]);
            mma_bf16(c, qa[0][1], bfh[2], bfh[3]);
            mma_bf16(c, qa[0][1], bfl[2], bfl[3]);
            mma_bf16(c, qa[1][1], bfh[2], bfh[3]);
            float e0 = __expf(c[0]), e1 = __expf(c[1]);
            float e2 = __expf(c[2]), e3 = __expf(c[3]);
            s0 += e0 + e1;
            s1 += e2 + e3;
            __half2 h01 = __floats2half2_rn(e0, e1);
            __half2 h23 = __floats2half2_rn(e2, e3);
            int col = kc*64 + wid*4 + kp;
            PU[ gr   *PH + col] = *(const uint32_t*)&h01;
            PU[(gr+8)*PH + col] = *(const uint32_t*)&h23;
        }
    }
    // row-sum reduction
    s0 += __shfl_xor_sync(0xffffffffu, s0, 1);
    s0 += __shfl_xor_sync(0xffffffffu, s0, 2);
    s1 += __shfl_xor_sync(0xffffffffu, s1, 1);
    s1 += __shfl_xor_sync(0xffffffffu, s1, 2);
    if (kp == 0) {
        red[wid*16 + gr]     = s0;
        red[wid*16 + gr + 8] = s1;
    }
    __syncthreads();
    if (tid < QT) {
        float s = 0.f;
        #pragma unroll
        for (int w = 0; w < 16; w++) s += red[w*16 + tid];
        inv[tid] = 1.0f / s;
    }
    __syncthreads();

    // prefetch V chunk 0 (overlaps with disc); 512 threads cover 32d x 128l
    const uint4* Gv4 = (const uint4*)g_VT16;
    const int vd = tid >> 4, vp4 = tid & 15;
    uint4 pv0 = Gv4[((size_t)bh*32 + vd)*256 + vp4];

    // ---- phase 2: discrepancy partials (e*inv, half2 reads) -------------------
    {
        size_t pbase = (((size_t)(b*HH + h))*128 + qt) * LL;
        #pragma unroll
        for (int t = 0; t < 2; t++) {
            int k2 = tid + t*512;
            int k  = k2*2;
            float2 acc = make_float2(0.f, 0.f);
            #pragma unroll
            for (int q = 0; q < QT; q++) {
                uint32_t pa = PU[q*PH + k2];
                __half2 h2 = *(const __half2*)&pa;
                float2 af = __half22float2(h2);
                float ivq = inv[q];
                float pr0 = Es[abs(q0 + q - k)]     * irs[q];
                float pr1 = Es[abs(q0 + q - k - 1)] * irs[q];
                acc.x += fabsf(af.x*ivq - pr0);
                acc.y += fabsf(af.y*ivq - pr1);
            }
            *(float2*)&g_dpart[pbase + k] = acc;
        }
    }

    // ---- phase 3: O = (e @ V) * inv via mma.f16 + ldmatrix (V single f16) -----
    {
        const int nt = wid & 3, seg = wid >> 2;
        uint32_t* Vhi = Kst;
        const uint32_t sbVhi = sbKst;
        float c[4] = {0.f,0.f,0.f,0.f};

        const int aq   = (lane & 7) + ((lane >> 3) & 1)*8;
        const int akof = (lane >> 4)*16;
        const int bl8  = lane & 15;
        const int bnrow = nt*8 + (bl8 & 7);
        const int bkof  = ((bl8 >> 3) & 1)*16;

        for (int ch = 0; ch < 16; ch++) {
            __syncthreads();
            *(uint4*)(Vhi + vd*68 + vp4*4) = pv0;
            __syncthreads();
            if (ch < 15) {
                pv0 = Gv4[((size_t)bh*32 + vd)*256 + (ch+1)*16 + vp4];
            }
            #pragma unroll
            for (int ks = 0; ks < 2; ks++) {
                int kbytes = (ch*64 + seg*16 + ks*8)*4;
                int vbytes = (seg*16 + ks*8)*4;
                uint32_t af[4], bfh[2];
                ldmx4(af, sbP + (uint32_t)aq*(PH*4) + kbytes + akof);
                ldmx2(bfh, sbVhi + (uint32_t)bnrow*272 + vbytes + bkof);
                mma_f16(c, af, bfh[0], bfh[1]);
            }
        }
        __syncthreads();     // Es region no longer needed -> Op
        int dcol = nt*8 + kp*2;
        Op[seg*512 +  gr   *32 + dcol]     = c[0];
        Op[seg*512 +  gr   *32 + dcol + 1] = c[1];
        Op[seg*512 + (gr+8)*32 + dcol]     = c[2];
        Op[seg*512 + (gr+8)*32 + dcol + 1] = c[3];
    }
    __syncthreads();
    {
        int q = tid >> 5, d = tid & 31;
        float s = (Op[q*32 + d] + Op[512 + q*32 + d]
                 + Op[1024 + q*32 + d] + Op[1536 + q*32 + d]) * inv[q];
        g_O[((size_t)bh*LL + q0 + q)*HD + d] = s;
    }
}

// ---------------- kernel 4: discrepancy reduce (2-stage) ----------------------
__global__ void disc_reduce1_kernel()
{
    int k = blockIdx.x*256 + threadIdx.x;
    int seg = blockIdx.y;
    int b = k >> 11, kk = k & (LL-1);
    const float* base = g_dpart + (size_t)b*HH*128*LL + kk;
    float s = 0.f;
    #pragma unroll 8
    for (int p = seg*64; p < seg*64 + 64; p++) s += base[(size_t)p*LL];
    g_dpart2[seg*BB*LL + k] = s;
}
__global__ void disc_reduce2_kernel(float* __restrict__ dout)
{
    int idx = blockIdx.x*256 + threadIdx.x;
    float s = 0.f;
    #pragma unroll
    for (int seg = 0; seg < 16; seg++) s += g_dpart2[seg*BB*LL + idx];
    dout[idx] = s * (1.0f/(HH*(float)LL));
}

// ---------------- kernel 5: out projection via mma ---------------------------
__global__ __launch_bounds__(256) void outproj_mma_kernel(
    const float* __restrict__ Wo, const float* __restrict__ bo,
    float* __restrict__ out)
{
    extern __shared__ uint32_t usm[];
    uint32_t* Xh = usm;
    uint32_t* Xl = usm + LK_XL;
    uint32_t* Wh = usm + LK_WH;
    uint32_t* Wl = usm + LK_WL;

    const int m0 = blockIdx.y*128, n0 = blockIdx.x*64;
    const int tid = threadIdx.x, wid = tid>>5, lane = tid&31;
    const int gr = lane>>2, kp = lane&3;

    float c[8][4] = {};
    for (int kc = 0; kc < 4; kc++) {
        __syncthreads();
        #pragma unroll
        for (int j = 0; j < 16; j++) {
            int u2 = tid + j*256;
            int r = u2 >> 5, cc = u2 & 31;
            int m = m0 + r;
            int b = m >> 11, l = m & (LL-1);
            int k = kc*64 + cc*2;
            int hh = k >> 5, d = k & 31;
            float2 v = *(const float2*)&g_O[(((size_t)(b*HH + hh))*LL + l)*HD + d];
            __nv_bfloat162 hb = __floats2bfloat162_rn(v.x, v.y);
            __nv_bfloat162 lb = __floats2bfloat162_rn(
                v.x - __bfloat162float(hb.x), v.y - __bfloat162float(hb.y));
            Xh[r*33 + cc] = *(const uint32_t*)&hb;
            Xl[r*33 + cc] = *(const uint32_t*)&lb;
        }
        #pragma unroll
        for (int j = 0; j < 8; j++) {
            int u2 = tid + j*256;
            int r = u2 >> 5, cc = u2 & 31;
            float2 v = *(const float2*)&Wo[(size_t)(n0+r)*DD + kc*64 + cc*2];
            __nv_bfloat162 hb = __floats2bfloat162_rn(v.x, v.y);
            __nv_bfloat162 lb = __floats2bfloat162_rn(
                v.x - __bfloat162float(hb.x), v.y - __bfloat162float(hb.y));
            Wh[r*33 + cc] = *(const uint32_t*)&hb;
            Wl[r*33 + cc] = *(const uint32_t*)&lb;
        }
        __syncthreads();
        #pragma unroll
        for (int s = 0; s < 4; s++) {
            const int mb = wid*16;
            uint32_t ah[4], al[4];
            ah[0] = Xh[(mb+gr  )*33 + s*8 + kp];
            ah[1] = Xh[(mb+gr+8)*33 + s*8 + kp];
            ah[2] = Xh[(mb+gr  )*33 + s*8 + kp + 4];
            ah[3] = Xh[(mb+gr+8)*33 + s*8 + kp + 4];
            al[0] = Xl[(mb+gr  )*33 + s*8 + kp];
            al[1] = Xl[(mb+gr+8)*33 + s*8 + kp];
            al[2] = Xl[(mb+gr  )*33 + s*8 + kp + 4];
            al[3] = Xl[(mb+gr+8)*33 + s*8 + kp + 4];
            #pragma unroll
            for (int nt = 0; nt < 8; nt++) {
                uint32_t bh0 = Wh[(nt*8+gr)*33 + s*8 + kp];
                uint32_t bh1 = Wh[(nt*8+gr)*33 + s*8 + kp + 4];
                uint32_t bl0 = Wl[(nt*8+gr)*33 + s*8 + kp];
                uint32_t bl1 = Wl[(nt*8+gr)*33 + s*8 + kp + 4];
                mma_bf16(c[nt], ah, bh0, bh1);
                mma_bf16(c[nt], ah, bl0, bl1);
                mma_bf16(c[nt], al, bh0, bh1);
            }
        }
    }
    #pragma unroll
    for (int nt = 0; nt < 8; nt++) {
        #pragma unroll
        for (int hf = 0; hf < 2; hf++) {
            int m = m0 + wid*16 + gr + hf*8;
            int n = n0 + nt*8 + kp*2;
            float2 o;
            o.x = c[nt][hf*2]     + bo[n];
            o.y = c[nt][hf*2 + 1] + bo[n+1];
            *(float2*)&out[(size_t)m*DD + n] = o;
        }
    }
}

// ---------------- launch --------------------------------------------------------
extern "C" void kernel_launch(void* const* d_in, const int* in_sizes, int n_in,
                              void* d_out, int out_size)
{
    const float* x  = (const float*)d_in[0];
    const float* Wq = (const float*)d_in[1];
    const float* bq = (const float*)d_in[2];
    const float* Wk = (const float*)d_in[3];
    const float* bk = (const float*)d_in[4];
    const float* Wv = (const float*)d_in[5];
    const float* bv = (const float*)d_in[6];
    const float* u  = (const float*)d_in[7];
    const float* Wo = (const float*)d_in[8];
    const float* bo = (const float*)d_in[9];
    float* out = (float*)d_out;

    cudaFuncSetAttribute(attn_fused_kernel,
                         cudaFuncAttributeMaxDynamicSharedMemorySize, SMF_BYTES);
    cudaFuncSetAttribute(qkv_mma_kernel,
                         cudaFuncAttributeMaxDynamicSharedMemorySize, LK_TOT*4);
    cudaFuncSetAttribute(outproj_mma_kernel,
                         cudaFuncAttributeMaxDynamicSharedMemorySize, LK_TOT*4);

    qkv_mma_kernel<<<dim3(DD/64, (BB*LL)/128, 3), 256, LK_TOT*4>>>(
        x, Wq, bq, Wk, bk, Wv, bv);
    vt_kernel<<<dim3(BH, LL/128), 256>>>();
    prior_kernel<<<HH, 256>>>(u);
    attn_fused_kernel<<<dim3(LL/QT, BH), 512, SMF_BYTES>>>();
    disc_reduce1_kernel<<<dim3((BB*LL)/256, 16), 256>>>();
    disc_reduce2_kernel<<<(BB*LL)/256, 256>>>(out + (size_t)BB*LL*DD);
    outproj_mma_kernel<<<dim3(DD/64, (BB*LL)/128), 256, LK_TOT*4>>>(Wo, bo, out);
}

// round 15
// speedup vs baseline: 1.6857x; 1.1418x over previous
#include <cuda_runtime.h>
#include <cuda_bf16.h>
#include <cuda_fp16.h>
#include <math.h>
#include <stdint.h>

#define BB 2
#define LL 2048
#define DD 256
#define HH 8
#define HD 32
#define BH (BB*HH)
#define QT 32
#define PH 1036        // P strip pitch in u32 (half2 pairs)

// ---------------- scratch (device globals; no allocation allowed) ----------
__device__ float         g_V  [(size_t)BH*LL*HD];
__device__ float         g_O  [(size_t)BH*LL*HD];
__device__ __nv_bfloat16 g_Q16[(size_t)BH*LL*64];    // rows [Qhi d0..31 | Qlo d0..31] (scaled)
__device__ __nv_bfloat16 g_K16[(size_t)BH*LL*64];    // rows [Khi | Klo]
__device__ __half        g_VT16[(size_t)BH*32*LL];   // [bh][d][l]  (single f16)
__device__ float         g_E  [HH*LL];
__device__ float         g_rs [HH*LL];
__device__ float         g_dpart[(size_t)BB*HH*64*LL];
__device__ float         g_dpart2[16*BB*LL];

// ---------------- helpers ----------------------------------------------------
__device__ __forceinline__ uint32_t smem_u32(const void* p){
    uint32_t a;
    asm("{ .reg .u64 t; cvta.to.shared.u64 t, %1; cvt.u32.u64 %0, t; }" : "=r"(a) : "l"(p));
    return a;
}
__device__ __forceinline__ void mma_bf16(float* c, const uint32_t* a,
                                         uint32_t b0, uint32_t b1){
    asm volatile(
        "mma.sync.aligned.m16n8k16.row.col.f32.bf16.bf16.f32 "
        "{%0,%1,%2,%3}, {%4,%5,%6,%7}, {%8,%9}, {%0,%1,%2,%3};"
        : "+f"(c[0]), "+f"(c[1]), "+f"(c[2]), "+f"(c[3])
        : "r"(a[0]), "r"(a[1]), "r"(a[2]), "r"(a[3]), "r"(b0), "r"(b1));
}
__device__ __forceinline__ void mma_f16(float* c, const uint32_t* a,
                                        uint32_t b0, uint32_t b1){
    asm volatile(
        "mma.sync.aligned.m16n8k16.row.col.f32.f16.f16.f32 "
        "{%0,%1,%2,%3}, {%4,%5,%6,%7}, {%8,%9}, {%0,%1,%2,%3};"
        : "+f"(c[0]), "+f"(c[1]), "+f"(c[2]), "+f"(c[3])
        : "r"(a[0]), "r"(a[1]), "r"(a[2]), "r"(a[3]), "r"(b0), "r"(b1));
}
__device__ __forceinline__ void ldmx4(uint32_t* r, uint32_t addr){
    asm volatile("ldmatrix.sync.aligned.m8n8.x4.shared.b16 {%0,%1,%2,%3}, [%4];"
        : "=r"(r[0]),"=r"(r[1]),"=r"(r[2]),"=r"(r[3]) : "r"(addr));
}
__device__ __forceinline__ void ldmx2(uint32_t* r, uint32_t addr){
    asm volatile("ldmatrix.sync.aligned.m8n8.x2.shared.b16 {%0,%1}, [%2];"
        : "=r"(r[0]),"=r"(r[1]) : "r"(addr));
}

// ---------------- kernel 1: QKV projection via mma (bf16 3-product split) ----
#define LK_XL (128*33)
#define LK_WH (2*128*33)
#define LK_WL (2*128*33 + 64*33)
#define LK_TOT (2*128*33 + 2*64*33)

__global__ __launch_bounds__(256) void qkv_mma_kernel(
    const float* __restrict__ x,
    const float* __restrict__ Wq, const float* __restrict__ bq,
    const float* __restrict__ Wk, const float* __restrict__ bk,
    const float* __restrict__ Wv, const float* __restrict__ bv)
{
    extern __shared__ uint32_t usm[];
    uint32_t* Xh = usm;
    uint32_t* Xl = usm + LK_XL;
    uint32_t* Wh = usm + LK_WH;
    uint32_t* Wl = usm + LK_WL;

    const float* Wm; const float* bm;
    if (blockIdx.z == 0)      { Wm=Wq; bm=bq; }
    else if (blockIdx.z == 1) { Wm=Wk; bm=bk; }
    else                      { Wm=Wv; bm=bv; }

    const int m0 = blockIdx.y*128, n0 = blockIdx.x*64;
    const int tid = threadIdx.x, wid = tid>>5, lane = tid&31;
    const int gr = lane>>2, kp = lane&3;

    float c[8][4] = {};
    for (int kc = 0; kc < 4; kc++) {
        __syncthreads();
        #pragma unroll
        for (int j = 0; j < 16; j++) {
            int u2 = tid + j*256;
            int r = u2 >> 5, cc = u2 & 31;
            float2 v = *(const float2*)&x[(size_t)(m0+r)*DD + kc*64 + cc*2];
            __nv_bfloat162 hb = __floats2bfloat162_rn(v.x, v.y);
            __nv_bfloat162 lb = __floats2bfloat162_rn(
                v.x - __bfloat162float(hb.x), v.y - __bfloat162float(hb.y));
            Xh[r*33 + cc] = *(const uint32_t*)&hb;
            Xl[r*33 + cc] = *(const uint32_t*)&lb;
        }
        #pragma unroll
        for (int j = 0; j < 8; j++) {
            int u2 = tid + j*256;
            int r = u2 >> 5, cc = u2 & 31;
            float2 v = *(const float2*)&Wm[(size_t)(n0+r)*DD + kc*64 + cc*2];
            __nv_bfloat162 hb = __floats2bfloat162_rn(v.x, v.y);
            __nv_bfloat162 lb = __floats2bfloat162_rn(
                v.x - __bfloat162float(hb.x), v.y - __bfloat162float(hb.y));
            Wh[r*33 + cc] = *(const uint32_t*)&hb;
            Wl[r*33 + cc] = *(const uint32_t*)&lb;
        }
        __syncthreads();
        #pragma unroll
        for (int s = 0; s < 4; s++) {
            const int mb = wid*16;
            uint32_t ah[4], al[4];
            ah[0] = Xh[(mb+gr  )*33 + s*8 + kp];
            ah[1] = Xh[(mb+gr+8)*33 + s*8 + kp];
            ah[2] = Xh[(mb+gr  )*33 + s*8 + kp + 4];
            ah[3] = Xh[(mb+gr+8)*33 + s*8 + kp + 4];
            al[0] = Xl[(mb+gr  )*33 + s*8 + kp];
            al[1] = Xl[(mb+gr+8)*33 + s*8 + kp];
            al[2] = Xl[(mb+gr  )*33 + s*8 + kp + 4];
            al[3] = Xl[(mb+gr+8)*33 + s*8 + kp + 4];
            #pragma unroll
            for (int nt = 0; nt < 8; nt++) {
                uint32_t bh0 = Wh[(nt*8+gr)*33 + s*8 + kp];
                uint32_t bh1 = Wh[(nt*8+gr)*33 + s*8 + kp + 4];
                uint32_t bl0 = Wl[(nt*8+gr)*33 + s*8 + kp];
                uint32_t bl1 = Wl[(nt*8+gr)*33 + s*8 + kp + 4];
                mma_bf16(c[nt], ah, bh0, bh1);
                mma_bf16(c[nt], ah, bl0, bl1);
                mma_bf16(c[nt], al, bh0, bh1);
            }
        }
    }
    const float SCALE = 0.17677669529663687f;
    #pragma unroll
    for (int nt = 0; nt < 8; nt++) {
        #pragma unroll
        for (int hf = 0; hf < 2; hf++) {
            int m = m0 + wid*16 + gr + hf*8;
            int b = m >> 11, l = m & (LL-1);
            #pragma unroll
            for (int e = 0; e < 2; e++) {
                int n = n0 + nt*8 + kp*2 + e;
                float v = c[nt][hf*2 + e] + bm[n];
                int h = n >> 5, d = n & 31;
                size_t row = (size_t)(b*HH + h)*LL + l;
                if (blockIdx.z == 0) {
                    float sv = v * SCALE;
                    __nv_bfloat16 hi = __float2bfloat16(sv);
                    g_Q16[row*64 + d]      = hi;
                    g_Q16[row*64 + 32 + d] = __float2bfloat16(sv - __bfloat162float(hi));
                } else if (blockIdx.z == 1) {
                    __nv_bfloat16 hi = __float2bfloat16(v);
                    g_K16[row*64 + d]      = hi;
                    g_K16[row*64 + 32 + d] = __float2bfloat16(v - __bfloat162float(hi));
                } else {
                    g_V[row*HD + d] = v;
                }
            }
        }
    }
}

// ---------------- kernel 1b: V transpose -> f16 (single) ---------------------
__global__ __launch_bounds__(256) void vt_kernel()
{
    __shared__ float Vsm[128][33];
    const int bh = blockIdx.x, l0 = blockIdx.y*128;
    const int tid = threadIdx.x;
    for (int idx = tid; idx < 128*32; idx += 256) {
        int i = idx >> 5, d = idx & 31;
        Vsm[i][d] = g_V[((size_t)bh*LL + l0 + i)*HD + d];
    }
    __syncthreads();
    for (int idx = tid; idx < 32*128; idx += 256) {
        int d = idx >> 7, i = idx & 127;
        g_VT16[((size_t)bh*32 + d)*LL + l0 + i] = __float2half_rn(Vsm[i][d]);
    }
}

// ---------------- kernel 2: prior tables via prefix sum ----------------------
__global__ __launch_bounds__(256) void prior_kernel(const float* __restrict__ u)
{
    __shared__ float Es[LL];
    __shared__ float Ps[LL];
    __shared__ float part[256];
    const int h = blockIdx.x, tid = threadIdx.x;
    float uv = u[h];
    float cc = 0.5f / (uv*uv + 1e-6f);
    #pragma unroll
    for (int j = 0; j < 8; j++) {
        int d = tid + j*256;
        float fd = (float)d;
        float e = expf(-(fd*fd)*cc);
        Es[d] = e;
        g_E[h*LL + d] = e;
    }
    __syncthreads();
    float s = 0.f;
    #pragma unroll
    for (int i = 0; i < 8; i++) s += Es[tid*8 + i];
    part[tid] = s;
    __syncthreads();
    if (tid == 0) {
        float run = 0.f;
        for (int i = 0; i < 256; i++) { run += part[i]; part[i] = run; }
    }
    __syncthreads();
    float run = (tid == 0) ? 0.f : part[tid-1];
    #pragma unroll
    for (int i = 0; i < 8; i++) {
        run += Es[tid*8 + i];
        Ps[tid*8 + i] = run;
    }
    __syncthreads();
    float e0 = Es[0];
    #pragma unroll
    for (int j = 0; j < 8; j++) {
        int q = tid + j*256;
        g_rs[h*LL + q] = Ps[q] + Ps[LL-1-q] - e0;
    }
}

// ---------------- kernel 3: FUSED scores(exp)+disc+AV, QT=32, 1024 thr -------
// SMEM (u32 units):
//  P strip  [0, 33152)        32 rows x PH (e as half2 pairs)
//  Kst      [33152, 38272)    K chunk (128 keys x 20 hi | +2560 lo)
//                             phase 3: V chunk 32d x 132, then Op 4096 f
//  Es       [38272, 40320)
//  Qst      [40320, 41376)    32 x 33
//  red      [41376, 41888)    32 warps x 16 rows
//  inv      [41888, 41920)
//  irs      [41920, 41952)
#define SMF_P    0
#define SMF_KST  33152
#define SMF_ES   38272
#define SMF_QST  40320
#define SMF_RED  41376
#define SMF_INV  41888
#define SMF_IRS  41920
#define SMF_TOT  41952
#define SMF_BYTES (SMF_TOT*4)

__global__ __launch_bounds__(1024,1) void attn_fused_kernel()
{
    extern __shared__ uint32_t usm2[];
    uint32_t* PU  = usm2 + SMF_P;
    uint32_t* Kst = usm2 + SMF_KST;
    float*    Es  = (float*)(usm2 + SMF_ES);
    uint32_t* Qst = usm2 + SMF_QST;
    float*    red = (float*)(usm2 + SMF_RED);
    float*    inv = (float*)(usm2 + SMF_INV);
    float*    irs = (float*)(usm2 + SMF_IRS);

    const uint32_t sb    = smem_u32(usm2);
    const uint32_t sbP   = sb;
    const uint32_t sbKst = sb + SMF_KST*4;

    const int tid = threadIdx.x, wid = tid >> 5, lane = tid & 31;
    const int gr = lane >> 2, kp = lane & 3;
    const int qt = blockIdx.x, bh = blockIdx.y;
    const int b = bh >> 3, h = bh & 7, q0 = qt * QT;
    const int mt = wid >> 4, ntile = wid & 15;

    // ---- phase 0 -------------------------------------------------------------
    {
        int r = tid >> 5, c = tid & 31;   // 32 rows x 32 u32 = 1024
        Qst[r*33 + c] = ((const uint32_t*)g_Q16)[((size_t)bh*LL + q0 + r)*32 + c];
    }
    #pragma unroll
    for (int j = 0; j < 2; j++) { int i = tid + j*1024; Es[i] = g_E[h*LL + i]; }
    if (tid < QT) irs[tid] = 1.0f / (g_rs[h*LL + q0 + tid] + 1e-6f);
    __syncthreads();

    uint32_t qa[2][2][4];
    #pragma unroll
    for (int p = 0; p < 2; p++){
        int base = p*16;
        #pragma unroll
        for (int s = 0; s < 2; s++){
            qa[p][s][0] = Qst[(mt*16 + gr    )*33 + base + kp     + 8*s];
            qa[p][s][1] = Qst[(mt*16 + gr + 8)*33 + base + kp     + 8*s];
            qa[p][s][2] = Qst[(mt*16 + gr    )*33 + base + kp + 4 + 8*s];
            qa[p][s][3] = Qst[(mt*16 + gr + 8)*33 + base + kp + 4 + 8*s];
        }
    }

    // ---- phase 1: scores -> e (f16), row sums; 16 chunks of 128 keys ----------
    float s0 = 0.f, s1 = 0.f;
    {
        const uint4* Gk4 = (const uint4*)g_K16;
        const size_t kbase = (size_t)bh*LL*8;
        const int g0 = tid;                 // 1024 uint4 per 128-key chunk
        const int dst0 = (g0>>3)*20 + (g0&3)*4 + ((g0>>2)&1)*2560;
        uint4 pk0 = Gk4[kbase + g0];
        const uint32_t baddr = sbKst + (uint32_t)(ntile*8 + (lane&7))*80
                             + (uint32_t)((lane>>3)&3)*16;

        for (int kc = 0; kc < 16; kc++) {
            __syncthreads();
            *(uint4*)(Kst + dst0) = pk0;
            __syncthreads();
            if (kc < 15) pk0 = Gk4[kbase + (kc+1)*1024 + g0];
            uint32_t bfh[4], bfl[4];
            ldmx4(bfh, baddr);
            ldmx4(bfl, baddr + 2560*4);
            float c[4] = {0.f,0.f,0.f,0.f};
            mma_bf16(c, qa[0][0], bfh[0], bfh[1]);
            mma_bf16(c, qa[0][0], bfl[0], bfl[1]);
            mma_bf16(c, qa[1][0], bfh[0], bfh[1]);
            mma_bf16(c, qa[0][1], bfh[2], bfh[3]);
            mma_bf16(c, qa[0][1], bfl[2], bfl[3]);
            mma_bf16(c, qa[1][1], bfh[2], bfh[3]);
            float e0 = __expf(c[0]), e1 = __expf(c[1]);
            float e2 = __expf(c[2]), e3 = __expf(c[3]);
            s0 += e0 + e1;
            s1 += e2 + e3;
            __half2 h01 = __floats2half2_rn(e0, e1);
            __half2 h23 = __floats2half2_rn(e2, e3);
            int col = kc*64 + ntile*4 + kp;
            PU[(mt*16 + gr    )*PH + col] = *(const uint32_t*)&h01;
            PU[(mt*16 + gr + 8)*PH + col] = *(const uint32_t*)&h23;
        }
    }
    // row-sum reduction (across kp lanes, then across the 16 n-tiles)
    s0 += __shfl_xor_sync(0xffffffffu, s0, 1);
    s0 += __shfl_xor_sync(0xffffffffu, s0, 2);
    s1 += __shfl_xor_sync(0xffffffffu, s1, 1);
    s1 += __shfl_xor_sync(0xffffffffu, s1, 2);
    if (kp == 0) {
        red[wid*16 + gr]     = s0;
        red[wid*16 + gr + 8] = s1;
    }
    __syncthreads();
    if (tid < QT) {
        int mtr = tid >> 4, rr = tid & 15;
        float s = 0.f;
        #pragma unroll
        for (int nt = 0; nt < 16; nt++) s += red[(mtr*16 + nt)*16 + rr];
        inv[tid] = 1.0f / s;
    }
    __syncthreads();

    // prefetch V chunk 0 (overlaps with disc); 1024 threads cover 32d x 256l
    const uint4* Gv4 = (const uint4*)g_VT16;
    const int vd = tid >> 5, vp4 = tid & 31;
    uint4 pv0 = Gv4[((size_t)bh*32 + vd)*256 + vp4];

    // ---- phase 2: discrepancy partials (e*inv, half2 reads) -------------------
    {
        size_t pbase = (((size_t)(b*HH + h))*64 + qt) * LL;
        int k2 = tid;
        int k  = k2*2;
        float2 acc = make_float2(0.f, 0.f);
        #pragma unroll
        for (int q = 0; q < QT; q++) {
            uint32_t pa = PU[q*PH + k2];
            __half2 h2 = *(const __half2*)&pa;
            float2 af = __half22float2(h2);
            float ivq = inv[q];
            float pr0 = Es[abs(q0 + q - k)]     * irs[q];
            float pr1 = Es[abs(q0 + q - k - 1)] * irs[q];
            acc.x += fabsf(af.x*ivq - pr0);
            acc.y += fabsf(af.y*ivq - pr1);
        }
        *(float2*)&g_dpart[pbase + k] = acc;
    }

    // ---- phase 3: O = (e @ V) * inv via mma.f16 + ldmatrix --------------------
    {
        const int nt = (wid >> 2) & 3, seg = wid & 3;   // with mt: 2x4x4 = 32 warps
        uint32_t* Vst = Kst;                            // 32 d x 132 u32
        const uint32_t sbV = sbKst;
        float c[4] = {0.f,0.f,0.f,0.f};

        const int aq   = (lane & 7) + ((lane >> 3) & 1)*8;
        const int akof = (lane >> 4)*16;
        const int bl8  = lane & 15;
        const int bnrow = nt*8 + (bl8 & 7);
        const int bkof  = ((bl8 >> 3) & 1)*16;

        for (int ch = 0; ch < 8; ch++) {                // 8 chunks x 256 l
            __syncthreads();
            *(uint4*)(Vst + vd*132 + vp4*4) = pv0;
            __syncthreads();
            if (ch < 7) pv0 = Gv4[((size_t)bh*32 + vd)*256 + (ch+1)*32 + vp4];
            #pragma unroll
            for (int ks = 0; ks < 4; ks++) {
                int kbytes = (ch*128 + seg*32 + ks*8)*4;
                int vbytes = (seg*32 + ks*8)*4;
                uint32_t af[4], bfh[2];
                ldmx4(af, sbP + (uint32_t)(mt*16 + aq)*(PH*4) + kbytes + akof);
                ldmx2(bfh, sbV + (uint32_t)bnrow*528 + vbytes + bkof);
                mma_f16(c, af, bfh[0], bfh[1]);
            }
        }
        __syncthreads();     // V staging done -> reuse Kst as Op (4 x 32q x 32d)
        float* Op = (float*)Kst;
        int dcol = nt*8 + kp*2;
        Op[seg*1024 + (mt*16 + gr    )*32 + dcol]     = c[0];
        Op[seg*1024 + (mt*16 + gr    )*32 + dcol + 1] = c[1];
        Op[seg*1024 + (mt*16 + gr + 8)*32 + dcol]     = c[2];
        Op[seg*1024 + (mt*16 + gr + 8)*32 + dcol + 1] = c[3];
    }
    __syncthreads();
    {
        float* Op = (float*)Kst;
        int q = tid >> 5, d = tid & 31;
        float s = (Op[q*32 + d] + Op[1024 + q*32 + d]
                 + Op[2048 + q*32 + d] + Op[3072 + q*32 + d]) * inv[q];
        g_O[((size_t)bh*LL + q0 + q)*HD + d] = s;
    }
}

// ---------------- kernel 4: discrepancy reduce (2-stage) ----------------------
__global__ void disc_reduce1_kernel()
{
    int k = blockIdx.x*256 + threadIdx.x;
    int seg = blockIdx.y;                   // 16 segments of 32 partials (HH*64=512)
    int b = k >> 11, kk = k & (LL-1);
    const float* base = g_dpart + (size_t)b*HH*64*LL + kk;
    float s = 0.f;
    #pragma unroll 8
    for (int p = seg*32; p < seg*32 + 32; p++) s += base[(size_t)p*LL];
    g_dpart2[seg*BB*LL + k] = s;
}
__global__ void disc_reduce2_kernel(float* __restrict__ dout)
{
    int idx = blockIdx.x*256 + threadIdx.x;
    float s = 0.f;
    #pragma unroll
    for (int seg = 0; seg < 16; seg++) s += g_dpart2[seg*BB*LL + idx];
    dout[idx] = s * (1.0f/(HH*(float)LL));
}

// ---------------- kernel 5: out projection via mma ---------------------------
__global__ __launch_bounds__(256) void outproj_mma_kernel(
    const float* __restrict__ Wo, const float* __restrict__ bo,
    float* __restrict__ out)
{
    extern __shared__ uint32_t usm[];
    uint32_t* Xh = usm;
    uint32_t* Xl = usm + LK_XL;
    uint32_t* Wh = usm + LK_WH;
    uint32_t* Wl = usm + LK_WL;

    const int m0 = blockIdx.y*128, n0 = blockIdx.x*64;
    const int tid = threadIdx.x, wid = tid>>5, lane = tid&31;
    const int gr = lane>>2, kp = lane&3;

    float c[8][4] = {};
    for (int kc = 0; kc < 4; kc++) {
        __syncthreads();
        #pragma unroll
        for (int j = 0; j < 16; j++) {
            int u2 = tid + j*256;
            int r = u2 >> 5, cc = u2 & 31;
            int m = m0 + r;
            int b = m >> 11, l = m & (LL-1);
            int k = kc*64 + cc*2;
            int hh = k >> 5, d = k & 31;
            float2 v = *(const float2*)&g_O[(((size_t)(b*HH + hh))*LL + l)*HD + d];
            __nv_bfloat162 hb = __floats2bfloat162_rn(v.x, v.y);
            __nv_bfloat162 lb = __floats2bfloat162_rn(
                v.x - __bfloat162float(hb.x), v.y - __bfloat162float(hb.y));
            Xh[r*33 + cc] = *(const uint32_t*)&hb;
            Xl[r*33 + cc] = *(const uint32_t*)&lb;
        }
        #pragma unroll
        for (int j = 0; j < 8; j++) {
            int u2 = tid + j*256;
            int r = u2 >> 5, cc = u2 & 31;
            float2 v = *(const float2*)&Wo[(size_t)(n0+r)*DD + kc*64 + cc*2];
            __nv_bfloat162 hb = __floats2bfloat162_rn(v.x, v.y);
            __nv_bfloat162 lb = __floats2bfloat162_rn(
                v.x - __bfloat162float(hb.x), v.y - __bfloat162float(hb.y));
            Wh[r*33 + cc] = *(const uint32_t*)&hb;
            Wl[r*33 + cc] = *(const uint32_t*)&lb;
        }
        __syncthreads();
        #pragma unroll
        for (int s = 0; s < 4; s++) {
            const int mb = wid*16;
            uint32_t ah[4], al[4];
            ah[0] = Xh[(mb+gr  )*33 + s*8 + kp];
            ah[1] = Xh[(mb+gr+8)*33 + s*8 + kp];
            ah[2] = Xh[(mb+gr  )*33 + s*8 + kp + 4];
            ah[3] = Xh[(mb+gr+8)*33 + s*8 + kp + 4];
            al[0] = Xl[(mb+gr  )*33 + s*8 + kp];
            al[1] = Xl[(mb+gr+8)*33 + s*8 + kp];
            al[2] = Xl[(mb+gr  )*33 + s*8 + kp + 4];
            al[3] = Xl[(mb+gr+8)*33 + s*8 + kp + 4];
            #pragma unroll
            for (int nt = 0; nt < 8; nt++) {
                uint32_t bh0 = Wh[(nt*8+gr)*33 + s*8 + kp];
                uint32_t bh1 = Wh[(nt*8+gr)*33 + s*8 + kp + 4];
                uint32_t bl0 = Wl[(nt*8+gr)*33 + s*8 + kp];
                uint32_t bl1 = Wl[(nt*8+gr)*33 + s*8 + kp + 4];
                mma_bf16(c[nt], ah, bh0, bh1);
                mma_bf16(c[nt], ah, bl0, bl1);
                mma_bf16(c[nt], al, bh0, bh1);
            }
        }
    }
    #pragma unroll
    for (int nt = 0; nt < 8; nt++) {
        #pragma unroll
        for (int hf = 0; hf < 2; hf++) {
            int m = m0 + wid*16 + gr + hf*8;
            int n = n0 + nt*8 + kp*2;
            float2 o;
            o.x = c[nt][hf*2]     + bo[n];
            o.y = c[nt][hf*2 + 1] + bo[n+1];
            *(float2*)&out[(size_t)m*DD + n] = o;
        }
    }
}

// ---------------- launch --------------------------------------------------------
extern "C" void kernel_launch(void* const* d_in, const int* in_sizes, int n_in,
                              void* d_out, int out_size)
{
    const float* x  = (const float*)d_in[0];
    const float* Wq = (const float*)d_in[1];
    const float* bq = (const float*)d_in[2];
    const float* Wk = (const float*)d_in[3];
    const float* bk = (const float*)d_in[4];
    const float* Wv = (const float*)d_in[5];
    const float* bv = (const float*)d_in[6];
    const float* u  = (const float*)d_in[7];
    const float* Wo = (const float*)d_in[8];
    const float* bo = (const float*)d_in[9];
    float* out = (float*)d_out;

    cudaFuncSetAttribute(attn_fused_kernel,
                         cudaFuncAttributeMaxDynamicSharedMemorySize, SMF_BYTES);
    cudaFuncSetAttribute(qkv_mma_kernel,
                         cudaFuncAttributeMaxDynamicSharedMemorySize, LK_TOT*4);
    cudaFuncSetAttribute(outproj_mma_kernel,
                         cudaFuncAttributeMaxDynamicSharedMemorySize, LK_TOT*4);

    qkv_mma_kernel<<<dim3(DD/64, (BB*LL)/128, 3), 256, LK_TOT*4>>>(
        x, Wq, bq, Wk, bk, Wv, bv);
    vt_kernel<<<dim3(BH, LL/128), 256>>>();
    prior_kernel<<<HH, 256>>>(u);
    attn_fused_kernel<<<dim3(LL/QT, BH), 1024, SMF_BYTES>>>();
    disc_reduce1_kernel<<<dim3((BB*LL)/256, 16), 256>>>();
    disc_reduce2_kernel<<<(BB*LL)/256, 256>>>(out + (size_t)BB*LL*DD);
    outproj_mma_kernel<<<dim3(DD/64, (BB*LL)/128), 256, LK_TOT*4>>>(Wo, bo, out);
}